// round 6
// baseline (speedup 1.0000x reference)
#include <cuda_runtime.h>
#include <cstdint>
#include <math.h>

// ---------------------------------------------------------------------------
// Problem constants
// ---------------------------------------------------------------------------
constexpr int B_  = 4;
constexpr int L_  = 2048;
constexpr int D_  = 512;
constexpr int H_  = 1024;   // 2*D
constexpr int S_  = 16;
constexpr int M_  = B_ * L_;        // 8192 tokens
constexpr int H2_ = 2 * H_;         // 2048
constexpr int KSP_ = 4;             // split-K factor for the zc GEMM

// ---------------------------------------------------------------------------
// Scratch (device globals; no allocation allowed)
// ---------------------------------------------------------------------------
__device__ float g_cln[M_ * D_];
__device__ float g_z  [M_ * H2_];
__device__ float g_u  [M_ * H_];
__device__ float g_v  [M_ * H_];
__device__ float g_uc [M_ * H_];
__device__ float g_zcp[KSP_ * M_ * 64];   // split-K partials
__device__ float g_zc [M_ * 64];
__device__ float g_dt [M_ * H_];
__device__ float g_yv [M_ * H_];
// tf32-rounded copies of inputs that feed GEMMs
__device__ float g_xr [M_ * D_];
__device__ float g_wa [H2_ * D_];
__device__ float g_wgb[H_ * D_];
__device__ float g_wgc[H_ * D_];
__device__ float g_wc [64 * H_];
__device__ float g_we [H_ * 32];
__device__ float g_wi [D_ * H_];

// ---------------------------------------------------------------------------
// Helpers
// ---------------------------------------------------------------------------
__device__ __forceinline__ uint32_t smem_u32(const void* p) {
    uint32_t a;
    asm("{ .reg .u64 t; cvta.to.shared.u64 t, %1; cvt.u32.u64 %0, t; }"
        : "=r"(a) : "l"(p));
    return a;
}
__device__ __forceinline__ void cpa16(uint32_t dst, const void* src) {
    asm volatile("cp.async.cg.shared.global [%0], [%1], 16;"
                 :: "r"(dst), "l"(src));
}
// round fp32 -> tf32 (result is fp32 bits with low 13 mantissa bits zero)
__device__ __forceinline__ float tf32r(float x) {
    uint32_t r;
    asm("cvt.rna.tf32.f32 %0, %1;" : "=r"(r) : "f"(x));
    return __uint_as_float(r);
}
__device__ __forceinline__ void mma_tf32_16x8x8(float c[4],
                                                const uint32_t a[4],
                                                const uint32_t b[2]) {
    asm volatile(
        "mma.sync.aligned.m16n8k8.row.col.f32.tf32.tf32.f32 "
        "{%0,%1,%2,%3}, {%4,%5,%6,%7}, {%8,%9}, {%0,%1,%2,%3};"
        : "+f"(c[0]), "+f"(c[1]), "+f"(c[2]), "+f"(c[3])
        : "r"(a[0]), "r"(a[1]), "r"(a[2]), "r"(a[3]),
          "r"(b[0]), "r"(b[1]));
}

// ---------------------------------------------------------------------------
// Elementwise tf32 rounding pass (for x and the weight matrices)
// ---------------------------------------------------------------------------
__global__ void round_kernel(const float* __restrict__ in,
                             float* __restrict__ out, int n4)
{
    const int i = blockIdx.x * blockDim.x + threadIdx.x;
    if (i >= n4) return;
    float4 a = ((const float4*)in)[i];
    a.x = tf32r(a.x); a.y = tf32r(a.y); a.z = tf32r(a.z); a.w = tf32r(a.w);
    ((float4*)out)[i] = a;
}

// ---------------------------------------------------------------------------
// tf32 mma.sync GEMM:  C[m,n] = sum_k A[m,k] * W[n,k]  (+bias, +epilogue)
// A and W MUST already be tf32-rounded (low mantissa bits zero) — fragments
// are fed to the MMA as raw bits, no cvt in the inner loop.
// Block 128 x (NT*32), 8 warps (2x4), warp tile 64 x (NT*8), BK = 8,
// 3-stage cp.async pipeline, ONE __syncthreads per k-tile.
// ACT: 0 identity  1 softplus  2 u-gate (z1*(1+sigmoid(.)))  3 v-add (z2+.)
// KSPLIT > 1: blockIdx.x selects a K-chunk, n0 = 0, C += bx * M_ * ldc.
// ---------------------------------------------------------------------------
template<int ACT, int NT, int KSPLIT>
__global__ __launch_bounds__(256)
void mma_gemm(const float* __restrict__ A, int lda,
              const float* __restrict__ W, int ldw,
              const float* __restrict__ bias,
              const float* __restrict__ EX,
              float* __restrict__ C, int ldc, int K)
{
    constexpr int BN = NT * 32;               // 128 or 64
    __shared__ float As[3][128][12];
    __shared__ float Bs[3][BN][12];

    const int tid  = threadIdx.x;
    const int warp = tid >> 5, lane = tid & 31;
    const int gid  = lane >> 2, tig = lane & 3;
    const int wm   = warp & 1,  wn  = warp >> 1;
    const int m0   = blockIdx.y * 128;

    int n0, koff, keff;
    if (KSPLIT > 1) {
        n0   = 0;
        keff = K / KSPLIT;
        koff = blockIdx.x * keff;
        C   += (size_t)blockIdx.x * M_ * ldc;
    } else {
        n0   = blockIdx.x * BN;
        keff = K;
        koff = 0;
    }
    const int mbase = wm * 64;
    const int nbase = wn * (NT * 8);

    float c[4][NT][4];
    #pragma unroll
    for (int i = 0; i < 4; i++)
        #pragma unroll
        for (int j = 0; j < NT; j++)
            #pragma unroll
            for (int q = 0; q < 4; q++) c[i][j][q] = 0.f;

    // gmem -> smem load assignment (16B per cp.async)
    const int arow = tid >> 1, acol = (tid & 1) * 4;
    const float* aptr = A + (size_t)(m0 + arow) * lda + koff + acol;
    const bool  bload = (arow < BN);
    const float* bptr = bload ? (W + (size_t)(n0 + arow) * ldw + koff + acol)
                              : nullptr;

    uint32_t adst[3], bdst[3];
    #pragma unroll
    for (int t = 0; t < 3; t++) {
        adst[t] = smem_u32(&As[t][arow][acol]);
        bdst[t] = bload ? smem_u32(&Bs[t][arow][acol]) : 0u;
    }

    const int nk = keff >> 3;

    auto issue_stage = [&](int t) {
        if (t < nk) {
            cpa16(adst[t % 3], aptr + (size_t)t * 8);
            if (bload) cpa16(bdst[t % 3], bptr + (size_t)t * 8);
        }
        asm volatile("cp.async.commit_group;" ::: "memory");
    };

    issue_stage(0);
    issue_stage(1);

    for (int kt = 0; kt < nk; ++kt) {
        asm volatile("cp.async.wait_group 1;" ::: "memory");
        __syncthreads();
        issue_stage(kt + 2);

        const int st = kt % 3;
        uint32_t af[4][4], bf[NT][2];
        #pragma unroll
        for (int ti = 0; ti < 4; ti++) {
            const int m = mbase + 16 * ti + gid;
            af[ti][0] = __float_as_uint(As[st][m    ][tig]);
            af[ti][1] = __float_as_uint(As[st][m + 8][tig]);
            af[ti][2] = __float_as_uint(As[st][m    ][tig + 4]);
            af[ti][3] = __float_as_uint(As[st][m + 8][tig + 4]);
        }
        #pragma unroll
        for (int tj = 0; tj < NT; tj++) {
            const int n = nbase + 8 * tj + gid;
            bf[tj][0] = __float_as_uint(Bs[st][n][tig]);
            bf[tj][1] = __float_as_uint(Bs[st][n][tig + 4]);
        }
        #pragma unroll
        for (int ti = 0; ti < 4; ti++)
            #pragma unroll
            for (int tj = 0; tj < NT; tj++)
                mma_tf32_16x8x8(c[ti][tj], af[ti], bf[tj]);
    }

    // epilogue
    #pragma unroll
    for (int ti = 0; ti < 4; ti++) {
        #pragma unroll
        for (int half = 0; half < 2; half++) {
            const int row = m0 + mbase + 16 * ti + gid + half * 8;
            #pragma unroll
            for (int tj = 0; tj < NT; tj++) {
                const int col = n0 + nbase + 8 * tj + 2 * tig;
                float v0 = c[ti][tj][half * 2 + 0];
                float v1 = c[ti][tj][half * 2 + 1];
                if (bias) { v0 += bias[col]; v1 += bias[col + 1]; }
                if (ACT == 1) {
                    v0 = (v0 > 20.f) ? v0 : log1pf(__expf(v0));
                    v1 = (v1 > 20.f) ? v1 : log1pf(__expf(v1));
                } else if (ACT == 2) {
                    const float z10 = EX[(size_t)row * H2_ + col];
                    const float z11 = EX[(size_t)row * H2_ + col + 1];
                    v0 = z10 * (1.f + 1.f / (1.f + __expf(-v0)));
                    v1 = z11 * (1.f + 1.f / (1.f + __expf(-v1)));
                } else if (ACT == 3) {
                    v0 += EX[(size_t)row * H2_ + H_ + col];
                    v1 += EX[(size_t)row * H2_ + H_ + col + 1];
                }
                float2 r; r.x = v0; r.y = v1;
                *(float2*)(C + (size_t)row * ldc + col) = r;
            }
        }
    }
}

// ---------------------------------------------------------------------------
// Reduce split-K partials; output rounded to tf32 (feeds the dt GEMM)
// ---------------------------------------------------------------------------
__global__ void zc_reduce(const float* __restrict__ zp,
                          float* __restrict__ zc)
{
    const int idx = blockIdx.x * blockDim.x + threadIdx.x;   // float4 index
    if (idx >= M_ * 64 / 4) return;
    const float4* p0 = (const float4*)zp + idx;
    float4 a = p0[0];
    #pragma unroll
    for (int j = 1; j < KSP_; j++) {
        const float4 bq = p0[(size_t)j * (M_ * 64 / 4)];
        a.x += bq.x; a.y += bq.y; a.z += bq.z; a.w += bq.w;
    }
    a.x = tf32r(a.x); a.y = tf32r(a.y); a.z = tf32r(a.z); a.w = tf32r(a.w);
    ((float4*)zc)[idx] = a;
}

// ---------------------------------------------------------------------------
// LayerNorm over D=512, one block (256 threads) per token.
// Output rounded to tf32 (feeds the gate GEMMs).
// ---------------------------------------------------------------------------
__global__ void ln_kernel(const float* __restrict__ ctx,
                          const float* __restrict__ w,
                          const float* __restrict__ b,
                          float* __restrict__ out)
{
    __shared__ float red[32];
    const int m = blockIdx.x;
    const int t = threadIdx.x;
    const float* xr = ctx + (size_t)m * D_;
    float v0 = xr[t], v1 = xr[t + 256];

    float s = v0 + v1;
    #pragma unroll
    for (int o = 16; o; o >>= 1) s += __shfl_xor_sync(0xffffffffu, s, o);
    if ((t & 31) == 0) red[t >> 5] = s;
    __syncthreads();
    if (t < 32) {
        float r = (t < 8) ? red[t] : 0.f;
        #pragma unroll
        for (int o = 4; o; o >>= 1) r += __shfl_xor_sync(0xffffffffu, r, o);
        if (t == 0) red[0] = r;
    }
    __syncthreads();
    const float mu = red[0] * (1.f / D_);
    const float d0 = v0 - mu, d1 = v1 - mu;

    float sq = d0 * d0 + d1 * d1;
    #pragma unroll
    for (int o = 16; o; o >>= 1) sq += __shfl_xor_sync(0xffffffffu, sq, o);
    __syncthreads();
    if ((t & 31) == 0) red[t >> 5] = sq;
    __syncthreads();
    if (t < 32) {
        float r = (t < 8) ? red[t] : 0.f;
        #pragma unroll
        for (int o = 4; o; o >>= 1) r += __shfl_xor_sync(0xffffffffu, r, o);
        if (t == 0) red[0] = r;
    }
    __syncthreads();
    const float inv = rsqrtf(red[0] * (1.f / D_) + 1e-5f);

    float* orow = out + (size_t)m * D_;
    orow[t]       = tf32r(d0 * inv * w[t]       + b[t]);
    orow[t + 256] = tf32r(d1 * inv * w[t + 256] + b[t + 256]);
}

// ---------------------------------------------------------------------------
// Causal depthwise conv3 + SiLU (float4-vectorized).
// Output rounded to tf32 (feeds the zc GEMM).
// ---------------------------------------------------------------------------
__global__ void conv_kernel(const float* __restrict__ u,
                            const float* __restrict__ cw,
                            const float* __restrict__ cb,
                            float* __restrict__ uc)
{
    const size_t i4 = (size_t)blockIdx.x * blockDim.x + threadIdx.x;
    if (i4 >= (size_t)M_ * H_ / 4) return;
    const size_t idx = i4 * 4;
    const int    h = (int)(idx % H_);
    const size_t m = idx / H_;
    const int    l = (int)(m % L_);

    const float4 x0  = *(const float4*)(u + idx);
    float4 xm1 = make_float4(0.f, 0.f, 0.f, 0.f);
    float4 xm2 = make_float4(0.f, 0.f, 0.f, 0.f);
    if (l >= 1) xm1 = *(const float4*)(u + idx - H_);
    if (l >= 2) xm2 = *(const float4*)(u + idx - 2 * H_);

    const float* x0p  = (const float*)&x0;
    const float* xm1p = (const float*)&xm1;
    const float* xm2p = (const float*)&xm2;
    float4 o;
    float* op = (float*)&o;
    #pragma unroll
    for (int q = 0; q < 4; q++) {
        const float r = cw[(h + q) * 3 + 0] * xm2p[q]
                      + cw[(h + q) * 3 + 1] * xm1p[q]
                      + cw[(h + q) * 3 + 2] * x0p[q] + cb[h + q];
        op[q] = tf32r(r / (1.f + __expf(-r)));   // silu, tf32-rounded
    }
    *(float4*)(uc + idx) = o;
}

// ---------------------------------------------------------------------------
// Selective scan, chunked (16 steps per chunk).
// One warp = 2 heads of one batch; lane = (hl = lane>>4, s = lane&15).
// Inner loop: 4 broadcasts/step, products kept per-lane; per-chunk 15-shfl
// multi-reduce transposes+sums the 16x16 block (lane s ends with y_{l0+s}).
// Output rounded to tf32 (feeds the out GEMM).
// ---------------------------------------------------------------------------
__global__ void scan_kernel(const float* __restrict__ uc,
                            const float* __restrict__ dt,
                            const float* __restrict__ zc,
                            const float* __restrict__ v,
                            const float* __restrict__ f_log,
                            const float* __restrict__ g,
                            float* __restrict__ yv)
{
    const int wid  = (int)((blockIdx.x * blockDim.x + threadIdx.x) >> 5);
    const int lane = threadIdx.x & 31;
    if (wid >= B_ * H_ / 2) return;
    const int b  = wid / (H_ / 2);
    const int h0 = (wid % (H_ / 2)) * 2;
    const int hl = lane >> 4;
    const int s  = lane & 15;          // state index; doubles as time-in-chunk
    const int h  = h0 + hl;

    const float a_hs = -__expf(f_log[h * S_ + s]);
    const float gd   = g[h];
    const float* zcb  = zc + (size_t)b * L_ * 64;
    const size_t baseH = (size_t)b * L_ * H_ + h;

    float bc0[16], dt0, uc0, vv0, du0;
    {
        #pragma unroll
        for (int j = 0; j < 16; j++)
            bc0[j] = zcb[(size_t)j * 64 + 32 + lane];
        const size_t o = baseH + (size_t)s * H_;
        dt0 = dt[o]; uc0 = uc[o]; vv0 = v[o];
        du0 = dt0 * uc0;
    }

    float x = 0.f;

    for (int l0 = 0; l0 < L_; l0 += 16) {
        float bc1[16], dt1, uc1, vv1, du1;
        if (l0 + 16 < L_) {
            #pragma unroll
            for (int j = 0; j < 16; j++)
                bc1[j] = zcb[(size_t)(l0 + 16 + j) * 64 + 32 + lane];
            const size_t o = baseH + (size_t)(l0 + 16 + s) * H_;
            dt1 = dt[o]; uc1 = uc[o]; vv1 = v[o];
            du1 = dt1 * uc1;
        } else { dt1 = uc1 = vv1 = du1 = 0.f; }

        float prod[16];
        #pragma unroll
        for (int j = 0; j < 16; j++) {
            const float dtq = __shfl_sync(0xffffffffu, dt0, hl * 16 + j);
            const float duq = __shfl_sync(0xffffffffu, du0, hl * 16 + j);
            const float bm  = __shfl_sync(0xffffffffu, bc0[j], s);
            const float cm  = __shfl_sync(0xffffffffu, bc0[j], 16 + s);

            const float aa = __expf(dtq * a_hs);
            x = fmaf(aa, x, duq * bm);
            prod[j] = x * cm;
        }

        // multi-reduce: 16 values over the 16-lane group (15 shfl total).
        // After stage 'off', lanes with (s&off)==0 hold the lower-half
        // outputs; final: lane s holds y for timestep l0+s.
        #pragma unroll
        for (int off = 8; off >= 1; off >>= 1) {
            #pragma unroll
            for (int j = 0; j < off; j++) {
                const float a = prod[j], bq = prod[j + off];
                const float send = (s & off) ? a : bq;
                const float t = __shfl_xor_sync(0xffffffffu, send, off);
                prod[j] = (s & off) ? (bq + t) : (a + t);
            }
        }

        const float sv = vv0 / (1.f + __expf(-vv0));
        yv[baseH + (size_t)(l0 + s) * H_] = tf32r((prod[0] + uc0 * gd) * sv);

        #pragma unroll
        for (int j = 0; j < 16; j++) bc0[j] = bc1[j];
        dt0 = dt1; uc0 = uc1; vv0 = vv1; du0 = du1;
    }
}

// ---------------------------------------------------------------------------
// Launch
// ---------------------------------------------------------------------------
extern "C" void kernel_launch(void* const* d_in, const int* in_sizes, int n_in,
                              void* d_out, int out_size)
{
    const float* x      = (const float*)d_in[0];
    const float* ctx    = (const float*)d_in[1];
    const float* Wa     = (const float*)d_in[2];
    const float* ba     = (const float*)d_in[3];
    const float* conv_w = (const float*)d_in[4];
    const float* conv_b = (const float*)d_in[5];
    const float* Wc     = (const float*)d_in[6];
    const float* We     = (const float*)d_in[7];
    const float* be     = (const float*)d_in[8];
    const float* f_log  = (const float*)d_in[9];
    const float* g      = (const float*)d_in[10];
    const float* Wi     = (const float*)d_in[11];
    const float* bi     = (const float*)d_in[12];
    const float* ln_w   = (const float*)d_in[13];
    const float* ln_b   = (const float*)d_in[14];
    const float* Wgb    = (const float*)d_in[15];
    const float* bgb    = (const float*)d_in[16];
    const float* Wgc    = (const float*)d_in[17];
    const float* bgc    = (const float*)d_in[18];
    float* out = (float*)d_out;

    float *cln, *z, *u, *v, *uc, *zcp, *zcb, *dtb, *yv;
    float *xr, *wa, *wgb, *wgc, *wc, *we, *wi;
    cudaGetSymbolAddress((void**)&cln, g_cln);
    cudaGetSymbolAddress((void**)&z,   g_z);
    cudaGetSymbolAddress((void**)&u,   g_u);
    cudaGetSymbolAddress((void**)&v,   g_v);
    cudaGetSymbolAddress((void**)&uc,  g_uc);
    cudaGetSymbolAddress((void**)&zcp, g_zcp);
    cudaGetSymbolAddress((void**)&zcb, g_zc);
    cudaGetSymbolAddress((void**)&dtb, g_dt);
    cudaGetSymbolAddress((void**)&yv,  g_yv);
    cudaGetSymbolAddress((void**)&xr,  g_xr);
    cudaGetSymbolAddress((void**)&wa,  g_wa);
    cudaGetSymbolAddress((void**)&wgb, g_wgb);
    cudaGetSymbolAddress((void**)&wgc, g_wgc);
    cudaGetSymbolAddress((void**)&wc,  g_wc);
    cudaGetSymbolAddress((void**)&we,  g_we);
    cudaGetSymbolAddress((void**)&wi,  g_wi);

    auto round_launch = [](const float* in, float* outp, int n) {
        round_kernel<<<(n / 4 + 255) / 256, 256>>>(in, outp, n / 4);
    };

    // 0. tf32-round x and all weight matrices into scratch
    round_launch(x,   xr,  M_ * D_);
    round_launch(Wa,  wa,  H2_ * D_);
    round_launch(Wgb, wgb, H_ * D_);
    round_launch(Wgc, wgc, H_ * D_);
    round_launch(Wc,  wc,  64 * H_);
    round_launch(We,  we,  H_ * 32);
    round_launch(Wi,  wi,  D_ * H_);

    // 1. LayerNorm(ctx) (tf32-rounded output)
    ln_kernel<<<M_, 256>>>(ctx, ln_w, ln_b, cln);

    // 2. z = x @ Wa^T + ba                      [8192, 2048]
    mma_gemm<0,4,1><<<dim3(H2_ / 128, M_ / 128), 256>>>(
        xr, D_, wa, D_, ba, nullptr, z, H2_, D_);

    // 3. u = z1 * (1 + sigmoid(cln @ Wgb^T + bgb))
    mma_gemm<2,4,1><<<dim3(H_ / 128, M_ / 128), 256>>>(
        cln, D_, wgb, D_, bgb, z, u, H_, D_);

    // 4. v = z2 + cln @ Wgc^T + bgc
    mma_gemm<3,4,1><<<dim3(H_ / 128, M_ / 128), 256>>>(
        cln, D_, wgc, D_, bgc, z, v, H_, D_);

    // 5. uc = silu(causal depthwise conv3(u))   (tf32-rounded output)
    conv_kernel<<<(int)(((size_t)M_ * H_ / 4 + 255) / 256), 256>>>(
        u, conv_w, conv_b, uc);

    // 6. zc = uc @ Wc^T  (split-K over 4 chunks, then reduce w/ tf32 round)
    mma_gemm<0,2,KSP_><<<dim3(KSP_, M_ / 128), 256>>>(
        uc, H_, wc, H_, nullptr, nullptr, zcp, 64, H_);
    zc_reduce<<<(M_ * 64 / 4 + 255) / 256, 256>>>(zcp, zcb);

    // 7. dt = softplus(zc[:, :R] @ We^T + be)   [8192, 1024]
    mma_gemm<1,4,1><<<dim3(H_ / 128, M_ / 128), 256>>>(
        zcb, 64, we, 32, be, nullptr, dtb, H_, 32);

    // 8. selective scan (fused skip + silu(v) gate; tf32-rounded output)
    scan_kernel<<<(B_ * H_ / 2) / 8, 256>>>(uc, dtb, zcb, v, f_log, g, yv);

    // 9. out = yv @ Wi^T + bi                   [8192, 512]
    mma_gemm<0,4,1><<<dim3(D_ / 128, M_ / 128), 256>>>(
        yv, H_, wi, H_, bi, nullptr, out, D_, H_);
}

// round 7
// speedup vs baseline: 1.0009x; 1.0009x over previous
#include <cuda_runtime.h>
#include <cstdint>
#include <math.h>

// ---------------------------------------------------------------------------
// Problem constants
// ---------------------------------------------------------------------------
constexpr int B_  = 4;
constexpr int L_  = 2048;
constexpr int D_  = 512;
constexpr int H_  = 1024;   // 2*D
constexpr int S_  = 16;
constexpr int M_  = B_ * L_;        // 8192 tokens
constexpr int H2_ = 2 * H_;         // 2048
constexpr int KSP_ = 4;             // split-K factor for the zc GEMM

// ---------------------------------------------------------------------------
// Scratch (device globals; no allocation allowed)
// ---------------------------------------------------------------------------
__device__ float g_cln[M_ * D_];
__device__ float g_z  [M_ * H2_];
__device__ float g_u  [M_ * H_];
__device__ float g_v  [M_ * H_];
__device__ float g_uc [M_ * H_];
__device__ float g_zcp[KSP_ * M_ * 64];   // split-K partials
__device__ float g_zc [M_ * 64];
__device__ float g_dt [M_ * H_];
__device__ float g_yv [M_ * H_];
// tf32-rounded copies of inputs that feed GEMMs
__device__ float g_xr [M_ * D_];
__device__ float g_wa [H2_ * D_];
__device__ float g_wgb[H_ * D_];
__device__ float g_wgc[H_ * D_];
__device__ float g_wc [64 * H_];
__device__ float g_we [H_ * 32];
__device__ float g_wi [D_ * H_];

// ---------------------------------------------------------------------------
// Helpers
// ---------------------------------------------------------------------------
__device__ __forceinline__ uint32_t smem_u32(const void* p) {
    uint32_t a;
    asm("{ .reg .u64 t; cvta.to.shared.u64 t, %1; cvt.u32.u64 %0, t; }"
        : "=r"(a) : "l"(p));
    return a;
}
__device__ __forceinline__ void cpa16(uint32_t dst, const void* src) {
    asm volatile("cp.async.cg.shared.global [%0], [%1], 16;"
                 :: "r"(dst), "l"(src));
}
// round fp32 -> tf32 (result is fp32 bits with low 13 mantissa bits zero)
__device__ __forceinline__ float tf32r(float x) {
    uint32_t r;
    asm("cvt.rna.tf32.f32 %0, %1;" : "=r"(r) : "f"(x));
    return __uint_as_float(r);
}
__device__ __forceinline__ void mma_tf32_16x8x8(float c[4],
                                                const uint32_t a[4],
                                                const uint32_t b[2]) {
    asm volatile(
        "mma.sync.aligned.m16n8k8.row.col.f32.tf32.tf32.f32 "
        "{%0,%1,%2,%3}, {%4,%5,%6,%7}, {%8,%9}, {%0,%1,%2,%3};"
        : "+f"(c[0]), "+f"(c[1]), "+f"(c[2]), "+f"(c[3])
        : "r"(a[0]), "r"(a[1]), "r"(a[2]), "r"(a[3]),
          "r"(b[0]), "r"(b[1]));
}

// ---------------------------------------------------------------------------
// Batched tf32 rounding (one kernel for x + all weight matrices)
// ---------------------------------------------------------------------------
struct RoundJob  { const float* src; float* dst; int n4; };
struct RoundJobs { RoundJob j[7]; };

__global__ void round_all(RoundJobs jobs)
{
    const RoundJob J = jobs.j[blockIdx.y];
    for (int i = blockIdx.x * blockDim.x + threadIdx.x; i < J.n4;
         i += gridDim.x * blockDim.x) {
        float4 a = ((const float4*)J.src)[i];
        a.x = tf32r(a.x); a.y = tf32r(a.y);
        a.z = tf32r(a.z); a.w = tf32r(a.w);
        ((float4*)J.dst)[i] = a;
    }
}

// ---------------------------------------------------------------------------
// tf32 mma.sync GEMM:  C[m,n] = sum_k A[m,k] * W[n,k]  (+bias, +epilogue)
// A and W MUST already be tf32-rounded — fragments are fed as raw bits.
// Block 128 x (NT*32), 8 warps (2x4), warp tile 64 x (NT*8).
// BK = 32 per stage (4 MMA k-steps), 2 smem stages, 2 syncs per stage
// (4x fewer barrier events than BK=8).  Smem row stride 36 with a 16-col
// rotation on odd 8-row groups -> conflict-free frag reads AND stores.
// ACT: 0 identity  1 softplus  2 u-gate (z1*(1+sigmoid(.)))  3 v-add (z2+.)
// KSPLIT > 1: blockIdx.x selects a K-chunk, n0 = 0, C += bx * M_ * ldc.
// ---------------------------------------------------------------------------
template<int ACT, int NT, int KSPLIT>
__global__ __launch_bounds__(256, 2)
void mma_gemm(const float* __restrict__ A, int lda,
              const float* __restrict__ W, int ldw,
              const float* __restrict__ bias,
              const float* __restrict__ EX,
              float* __restrict__ C, int ldc, int K)
{
    constexpr int BN   = NT * 32;            // 128 or 64
    constexpr int LDSM = 36;                 // padded row stride (floats)
    constexpr int BCH  = (BN * 32) / (256 * 4);   // B float4 chunks / thread
    extern __shared__ float sm[];
    float* Asm = sm;                          // [2][128][36]
    float* Bsm = sm + 2 * 128 * LDSM;         // [2][BN ][36]

    const int tid  = threadIdx.x;
    const int warp = tid >> 5, lane = tid & 31;
    const int gid  = lane >> 2, tig = lane & 3;
    const int wm   = warp & 1,  wn  = warp >> 1;
    const int m0   = blockIdx.y * 128;

    int n0, koff, keff;
    if (KSPLIT > 1) {
        n0   = 0;
        keff = K / KSPLIT;
        koff = blockIdx.x * keff;
        C   += (size_t)blockIdx.x * M_ * ldc;
    } else {
        n0   = blockIdx.x * BN;
        keff = K;
        koff = 0;
    }
    const int mbase = wm * 64;
    const int nbase = wn * (NT * 8);

    // swizzled smem accessors (16-col rotation on odd 8-row groups)
    auto sA = [&](int st, int row, int col) -> float* {
        return Asm + (st * 128 + row) * LDSM
                   + ((col + ((row >> 3) & 1) * 16) & 31);
    };
    auto sB = [&](int st, int row, int col) -> float* {
        return Bsm + (st * BN + row) * LDSM
                   + ((col + ((row >> 3) & 1) * 16) & 31);
    };

    float c[4][NT][4];
    #pragma unroll
    for (int i = 0; i < 4; i++)
        #pragma unroll
        for (int j = 0; j < NT; j++)
            #pragma unroll
            for (int q = 0; q < 4; q++) c[i][j][q] = 0.f;

    // gmem -> smem load slots: each thread owns 16 consecutive k-cols of
    // one A row (4 float4s) and 16 (or 8) of one B row.
    const int ar  = tid >> 1;
    const int acb = (tid & 1) * 16;
    const int br  = (BN == 128) ? (tid >> 1) : (tid >> 2);
    const int bcb = (BN == 128) ? (tid & 1) * 16 : (tid & 3) * 8;
    const float* aq = A + (size_t)(m0 + ar) * lda + koff + acb;
    const float* bq = W + (size_t)(n0 + br) * ldw + koff + bcb;

    uint32_t adst[2][4], bdst[2][BCH];
    #pragma unroll
    for (int st = 0; st < 2; st++) {
        #pragma unroll
        for (int c0 = 0; c0 < 4; c0++)
            adst[st][c0] = smem_u32(sA(st, ar, acb + 4 * c0));
        #pragma unroll
        for (int c0 = 0; c0 < BCH; c0++)
            bdst[st][c0] = smem_u32(sB(st, br, bcb + 4 * c0));
    }

    const int nk = keff >> 5;               // stages of BK=32

    auto issue_stage = [&](int t) {
        if (t < nk) {
            const int sb = t & 1;
            #pragma unroll
            for (int c0 = 0; c0 < 4; c0++)
                cpa16(adst[sb][c0], aq + (size_t)t * 32 + 4 * c0);
            #pragma unroll
            for (int c0 = 0; c0 < BCH; c0++)
                cpa16(bdst[sb][c0], bq + (size_t)t * 32 + 4 * c0);
        }
        asm volatile("cp.async.commit_group;" ::: "memory");
    };

    issue_stage(0);
    issue_stage(1);

    for (int kt = 0; kt < nk; ++kt) {
        asm volatile("cp.async.wait_group 1;" ::: "memory");
        __syncthreads();
        const int st = kt & 1;

        #pragma unroll
        for (int ks = 0; ks < 4; ks++) {
            uint32_t af[4][4], bf[NT][2];
            #pragma unroll
            for (int ti = 0; ti < 4; ti++) {
                const int m = mbase + 16 * ti + gid;
                af[ti][0] = __float_as_uint(*sA(st, m,     ks * 8 + tig));
                af[ti][1] = __float_as_uint(*sA(st, m + 8, ks * 8 + tig));
                af[ti][2] = __float_as_uint(*sA(st, m,     ks * 8 + tig + 4));
                af[ti][3] = __float_as_uint(*sA(st, m + 8, ks * 8 + tig + 4));
            }
            #pragma unroll
            for (int tj = 0; tj < NT; tj++) {
                const int n = nbase + 8 * tj + gid;
                bf[tj][0] = __float_as_uint(*sB(st, n, ks * 8 + tig));
                bf[tj][1] = __float_as_uint(*sB(st, n, ks * 8 + tig + 4));
            }
            #pragma unroll
            for (int ti = 0; ti < 4; ti++)
                #pragma unroll
                for (int tj = 0; tj < NT; tj++)
                    mma_tf32_16x8x8(c[ti][tj], af[ti], bf[tj]);
        }

        __syncthreads();                 // all reads of stage st done
        issue_stage(kt + 2);             // safe to overwrite buffer st
    }

    // epilogue
    #pragma unroll
    for (int ti = 0; ti < 4; ti++) {
        #pragma unroll
        for (int half = 0; half < 2; half++) {
            const int row = m0 + mbase + 16 * ti + gid + half * 8;
            #pragma unroll
            for (int tj = 0; tj < NT; tj++) {
                const int col = n0 + nbase + 8 * tj + 2 * tig;
                float v0 = c[ti][tj][half * 2 + 0];
                float v1 = c[ti][tj][half * 2 + 1];
                if (bias) { v0 += bias[col]; v1 += bias[col + 1]; }
                if (ACT == 1) {
                    v0 = (v0 > 20.f) ? v0 : log1pf(__expf(v0));
                    v1 = (v1 > 20.f) ? v1 : log1pf(__expf(v1));
                } else if (ACT == 2) {
                    const float z10 = EX[(size_t)row * H2_ + col];
                    const float z11 = EX[(size_t)row * H2_ + col + 1];
                    v0 = z10 * (1.f + 1.f / (1.f + __expf(-v0)));
                    v1 = z11 * (1.f + 1.f / (1.f + __expf(-v1)));
                } else if (ACT == 3) {
                    v0 += EX[(size_t)row * H2_ + H_ + col];
                    v1 += EX[(size_t)row * H2_ + H_ + col + 1];
                }
                float2 r; r.x = v0; r.y = v1;
                *(float2*)(C + (size_t)row * ldc + col) = r;
            }
        }
    }
}

constexpr int SMEM_NT4 = (2 * 128 * 36 + 2 * 128 * 36) * 4;   // 73728
constexpr int SMEM_NT2 = (2 * 128 * 36 + 2 * 64  * 36) * 4;   // 55296

// ---------------------------------------------------------------------------
// Reduce split-K partials; output rounded to tf32 (feeds the dt GEMM)
// ---------------------------------------------------------------------------
__global__ void zc_reduce(const float* __restrict__ zp,
                          float* __restrict__ zc)
{
    const int idx = blockIdx.x * blockDim.x + threadIdx.x;   // float4 index
    if (idx >= M_ * 64 / 4) return;
    const float4* p0 = (const float4*)zp + idx;
    float4 a = p0[0];
    #pragma unroll
    for (int j = 1; j < KSP_; j++) {
        const float4 bq = p0[(size_t)j * (M_ * 64 / 4)];
        a.x += bq.x; a.y += bq.y; a.z += bq.z; a.w += bq.w;
    }
    a.x = tf32r(a.x); a.y = tf32r(a.y); a.z = tf32r(a.z); a.w = tf32r(a.w);
    ((float4*)zc)[idx] = a;
}

// ---------------------------------------------------------------------------
// LayerNorm over D=512, one block (256 threads) per token.
// Output rounded to tf32 (feeds the gate GEMMs).
// ---------------------------------------------------------------------------
__global__ void ln_kernel(const float* __restrict__ ctx,
                          const float* __restrict__ w,
                          const float* __restrict__ b,
                          float* __restrict__ out)
{
    __shared__ float red[32];
    const int m = blockIdx.x;
    const int t = threadIdx.x;
    const float* xr = ctx + (size_t)m * D_;
    float v0 = xr[t], v1 = xr[t + 256];

    float s = v0 + v1;
    #pragma unroll
    for (int o = 16; o; o >>= 1) s += __shfl_xor_sync(0xffffffffu, s, o);
    if ((t & 31) == 0) red[t >> 5] = s;
    __syncthreads();
    if (t < 32) {
        float r = (t < 8) ? red[t] : 0.f;
        #pragma unroll
        for (int o = 4; o; o >>= 1) r += __shfl_xor_sync(0xffffffffu, r, o);
        if (t == 0) red[0] = r;
    }
    __syncthreads();
    const float mu = red[0] * (1.f / D_);
    const float d0 = v0 - mu, d1 = v1 - mu;

    float sq = d0 * d0 + d1 * d1;
    #pragma unroll
    for (int o = 16; o; o >>= 1) sq += __shfl_xor_sync(0xffffffffu, sq, o);
    __syncthreads();
    if ((t & 31) == 0) red[t >> 5] = sq;
    __syncthreads();
    if (t < 32) {
        float r = (t < 8) ? red[t] : 0.f;
        #pragma unroll
        for (int o = 4; o; o >>= 1) r += __shfl_xor_sync(0xffffffffu, r, o);
        if (t == 0) red[0] = r;
    }
    __syncthreads();
    const float inv = rsqrtf(red[0] * (1.f / D_) + 1e-5f);

    float* orow = out + (size_t)m * D_;
    orow[t]       = tf32r(d0 * inv * w[t]       + b[t]);
    orow[t + 256] = tf32r(d1 * inv * w[t + 256] + b[t + 256]);
}

// ---------------------------------------------------------------------------
// Causal depthwise conv3 + SiLU (float4-vectorized).
// Output rounded to tf32 (feeds the zc GEMM).
// ---------------------------------------------------------------------------
__global__ void conv_kernel(const float* __restrict__ u,
                            const float* __restrict__ cw,
                            const float* __restrict__ cb,
                            float* __restrict__ uc)
{
    const size_t i4 = (size_t)blockIdx.x * blockDim.x + threadIdx.x;
    if (i4 >= (size_t)M_ * H_ / 4) return;
    const size_t idx = i4 * 4;
    const int    h = (int)(idx % H_);
    const size_t m = idx / H_;
    const int    l = (int)(m % L_);

    const float4 x0  = *(const float4*)(u + idx);
    float4 xm1 = make_float4(0.f, 0.f, 0.f, 0.f);
    float4 xm2 = make_float4(0.f, 0.f, 0.f, 0.f);
    if (l >= 1) xm1 = *(const float4*)(u + idx - H_);
    if (l >= 2) xm2 = *(const float4*)(u + idx - 2 * H_);

    const float* x0p  = (const float*)&x0;
    const float* xm1p = (const float*)&xm1;
    const float* xm2p = (const float*)&xm2;
    float4 o;
    float* op = (float*)&o;
    #pragma unroll
    for (int q = 0; q < 4; q++) {
        const float r = cw[(h + q) * 3 + 0] * xm2p[q]
                      + cw[(h + q) * 3 + 1] * xm1p[q]
                      + cw[(h + q) * 3 + 2] * x0p[q] + cb[h + q];
        op[q] = tf32r(r / (1.f + __expf(-r)));   // silu, tf32-rounded
    }
    *(float4*)(uc + idx) = o;
}

// ---------------------------------------------------------------------------
// Selective scan, chunked (16 steps per chunk).
// One warp = 2 heads of one batch; lane = (hl = lane>>4, s = lane&15).
// ---------------------------------------------------------------------------
__global__ void scan_kernel(const float* __restrict__ uc,
                            const float* __restrict__ dt,
                            const float* __restrict__ zc,
                            const float* __restrict__ v,
                            const float* __restrict__ f_log,
                            const float* __restrict__ g,
                            float* __restrict__ yv)
{
    const int wid  = (int)((blockIdx.x * blockDim.x + threadIdx.x) >> 5);
    const int lane = threadIdx.x & 31;
    if (wid >= B_ * H_ / 2) return;
    const int b  = wid / (H_ / 2);
    const int h0 = (wid % (H_ / 2)) * 2;
    const int hl = lane >> 4;
    const int s  = lane & 15;          // state index; doubles as time-in-chunk
    const int h  = h0 + hl;

    const float a_hs = -__expf(f_log[h * S_ + s]);
    const float gd   = g[h];
    const float* zcb  = zc + (size_t)b * L_ * 64;
    const size_t baseH = (size_t)b * L_ * H_ + h;

    float bc0[16], dt0, uc0, vv0, du0;
    {
        #pragma unroll
        for (int j = 0; j < 16; j++)
            bc0[j] = zcb[(size_t)j * 64 + 32 + lane];
        const size_t o = baseH + (size_t)s * H_;
        dt0 = dt[o]; uc0 = uc[o]; vv0 = v[o];
        du0 = dt0 * uc0;
    }

    float x = 0.f;

    for (int l0 = 0; l0 < L_; l0 += 16) {
        float bc1[16], dt1, uc1, vv1, du1;
        if (l0 + 16 < L_) {
            #pragma unroll
            for (int j = 0; j < 16; j++)
                bc1[j] = zcb[(size_t)(l0 + 16 + j) * 64 + 32 + lane];
            const size_t o = baseH + (size_t)(l0 + 16 + s) * H_;
            dt1 = dt[o]; uc1 = uc[o]; vv1 = v[o];
            du1 = dt1 * uc1;
        } else { dt1 = uc1 = vv1 = du1 = 0.f; }

        float prod[16];
        #pragma unroll
        for (int j = 0; j < 16; j++) {
            const float dtq = __shfl_sync(0xffffffffu, dt0, hl * 16 + j);
            const float duq = __shfl_sync(0xffffffffu, du0, hl * 16 + j);
            const float bm  = __shfl_sync(0xffffffffu, bc0[j], s);
            const float cm  = __shfl_sync(0xffffffffu, bc0[j], 16 + s);

            const float aa = __expf(dtq * a_hs);
            x = fmaf(aa, x, duq * bm);
            prod[j] = x * cm;
        }

        // 16-value multi-reduce over the 16-lane group (15 shfl total);
        // final: lane s holds y for timestep l0+s.
        #pragma unroll
        for (int off = 8; off >= 1; off >>= 1) {
            #pragma unroll
            for (int j = 0; j < off; j++) {
                const float a = prod[j], bq = prod[j + off];
                const float send = (s & off) ? a : bq;
                const float t = __shfl_xor_sync(0xffffffffu, send, off);
                prod[j] = (s & off) ? (bq + t) : (a + t);
            }
        }

        const float sv = vv0 / (1.f + __expf(-vv0));
        yv[baseH + (size_t)(l0 + s) * H_] = tf32r((prod[0] + uc0 * gd) * sv);

        #pragma unroll
        for (int j = 0; j < 16; j++) bc0[j] = bc1[j];
        dt0 = dt1; uc0 = uc1; vv0 = vv1; du0 = du1;
    }
}

// ---------------------------------------------------------------------------
// Launch
// ---------------------------------------------------------------------------
extern "C" void kernel_launch(void* const* d_in, const int* in_sizes, int n_in,
                              void* d_out, int out_size)
{
    const float* x      = (const float*)d_in[0];
    const float* ctx    = (const float*)d_in[1];
    const float* Wa     = (const float*)d_in[2];
    const float* ba     = (const float*)d_in[3];
    const float* conv_w = (const float*)d_in[4];
    const float* conv_b = (const float*)d_in[5];
    const float* Wc     = (const float*)d_in[6];
    const float* We     = (const float*)d_in[7];
    const float* be     = (const float*)d_in[8];
    const float* f_log  = (const float*)d_in[9];
    const float* g      = (const float*)d_in[10];
    const float* Wi     = (const float*)d_in[11];
    const float* bi     = (const float*)d_in[12];
    const float* ln_w   = (const float*)d_in[13];
    const float* ln_b   = (const float*)d_in[14];
    const float* Wgb    = (const float*)d_in[15];
    const float* bgb    = (const float*)d_in[16];
    const float* Wgc    = (const float*)d_in[17];
    const float* bgc    = (const float*)d_in[18];
    float* out = (float*)d_out;

    float *cln, *z, *u, *v, *uc, *zcp, *zcb, *dtb, *yv;
    float *xr, *wa, *wgb, *wgc, *wc, *we, *wi;
    cudaGetSymbolAddress((void**)&cln, g_cln);
    cudaGetSymbolAddress((void**)&z,   g_z);
    cudaGetSymbolAddress((void**)&u,   g_u);
    cudaGetSymbolAddress((void**)&v,   g_v);
    cudaGetSymbolAddress((void**)&uc,  g_uc);
    cudaGetSymbolAddress((void**)&zcp, g_zcp);
    cudaGetSymbolAddress((void**)&zcb, g_zc);
    cudaGetSymbolAddress((void**)&dtb, g_dt);
    cudaGetSymbolAddress((void**)&yv,  g_yv);
    cudaGetSymbolAddress((void**)&xr,  g_xr);
    cudaGetSymbolAddress((void**)&wa,  g_wa);
    cudaGetSymbolAddress((void**)&wgb, g_wgb);
    cudaGetSymbolAddress((void**)&wgc, g_wgc);
    cudaGetSymbolAddress((void**)&wc,  g_wc);
    cudaGetSymbolAddress((void**)&we,  g_we);
    cudaGetSymbolAddress((void**)&wi,  g_wi);

    cudaFuncSetAttribute(mma_gemm<0,4,1>,
        cudaFuncAttributeMaxDynamicSharedMemorySize, SMEM_NT4);
    cudaFuncSetAttribute(mma_gemm<1,4,1>,
        cudaFuncAttributeMaxDynamicSharedMemorySize, SMEM_NT4);
    cudaFuncSetAttribute(mma_gemm<2,4,1>,
        cudaFuncAttributeMaxDynamicSharedMemorySize, SMEM_NT4);
    cudaFuncSetAttribute(mma_gemm<3,4,1>,
        cudaFuncAttributeMaxDynamicSharedMemorySize, SMEM_NT4);
    cudaFuncSetAttribute(mma_gemm<0,2,KSP_>,
        cudaFuncAttributeMaxDynamicSharedMemorySize, SMEM_NT2);

    // 0. tf32-round x and all weight matrices (one batched kernel)
    RoundJobs rj;
    rj.j[0] = { x,   xr,  M_ * D_   / 4 };
    rj.j[1] = { Wa,  wa,  H2_ * D_  / 4 };
    rj.j[2] = { Wgb, wgb, H_ * D_   / 4 };
    rj.j[3] = { Wgc, wgc, H_ * D_   / 4 };
    rj.j[4] = { Wc,  wc,  64 * H_   / 4 };
    rj.j[5] = { We,  we,  H_ * 32   / 4 };
    rj.j[6] = { Wi,  wi,  D_ * H_   / 4 };
    round_all<<<dim3(1024, 7), 256>>>(rj);

    // 1. LayerNorm(ctx) (tf32-rounded output)
    ln_kernel<<<M_, 256>>>(ctx, ln_w, ln_b, cln);

    // 2. z = x @ Wa^T + ba                      [8192, 2048]
    mma_gemm<0,4,1><<<dim3(H2_ / 128, M_ / 128), 256, SMEM_NT4>>>(
        xr, D_, wa, D_, ba, nullptr, z, H2_, D_);

    // 3. u = z1 * (1 + sigmoid(cln @ Wgb^T + bgb))
    mma_gemm<2,4,1><<<dim3(H_ / 128, M_ / 128), 256, SMEM_NT4>>>(
        cln, D_, wgb, D_, bgb, z, u, H_, D_);

    // 4. v = z2 + cln @ Wgc^T + bgc
    mma_gemm<3,4,1><<<dim3(H_ / 128, M_ / 128), 256, SMEM_NT4>>>(
        cln, D_, wgc, D_, bgc, z, v, H_, D_);

    // 5. uc = silu(causal depthwise conv3(u))   (tf32-rounded output)
    conv_kernel<<<(int)(((size_t)M_ * H_ / 4 + 255) / 256), 256>>>(
        u, conv_w, conv_b, uc);

    // 6. zc = uc @ Wc^T  (split-K over 4 chunks, then reduce w/ tf32 round)
    mma_gemm<0,2,KSP_><<<dim3(KSP_, M_ / 128), 256, SMEM_NT2>>>(
        uc, H_, wc, H_, nullptr, nullptr, zcp, 64, H_);
    zc_reduce<<<(M_ * 64 / 4 + 255) / 256, 256>>>(zcp, zcb);

    // 7. dt = softplus(zc[:, :R] @ We^T + be)   [8192, 1024]
    mma_gemm<1,4,1><<<dim3(H_ / 128, M_ / 128), 256, SMEM_NT4>>>(
        zcb, 64, we, 32, be, nullptr, dtb, H_, 32);

    // 8. selective scan (fused skip + silu(v) gate; tf32-rounded output)
    scan_kernel<<<(B_ * H_ / 2) / 8, 256>>>(uc, dtb, zcb, v, f_log, g, yv);

    // 9. out = yv @ Wi^T + bi                   [8192, 512]
    mma_gemm<0,4,1><<<dim3(D_ / 128, M_ / 128), 256, SMEM_NT4>>>(
        yv, H_, wi, H_, bi, nullptr, out, D_, H_);
}

// round 8
// speedup vs baseline: 1.1358x; 1.1348x over previous
#include <cuda_runtime.h>
#include <cstdint>
#include <math.h>

// ---------------------------------------------------------------------------
// Problem constants
// ---------------------------------------------------------------------------
constexpr int B_  = 4;
constexpr int L_  = 2048;
constexpr int D_  = 512;
constexpr int H_  = 1024;   // 2*D
constexpr int S_  = 16;
constexpr int M_  = B_ * L_;        // 8192 tokens
constexpr int H2_ = 2 * H_;         // 2048
constexpr int KSP_ = 4;             // split-K factor for the zc GEMM

// ---------------------------------------------------------------------------
// Scratch (device globals; no allocation allowed)
// ---------------------------------------------------------------------------
__device__ float g_cln[M_ * D_];
__device__ float g_z  [M_ * H2_];
__device__ float g_u  [M_ * H_];
__device__ float g_v  [M_ * H_];
__device__ float g_uc [M_ * H_];
__device__ float g_zcp[KSP_ * M_ * 64];   // split-K partials
__device__ float g_zc [M_ * 64];
__device__ float g_dt [M_ * H_];
__device__ float g_yv [M_ * H_];
// tf32-rounded copies of inputs that feed GEMMs
__device__ float g_xr [M_ * D_];
__device__ float g_wa [H2_ * D_];
__device__ float g_wgb[H_ * D_];
__device__ float g_wgc[H_ * D_];
__device__ float g_wc [64 * H_];
__device__ float g_we [H_ * 32];
__device__ float g_wi [D_ * H_];

// ---------------------------------------------------------------------------
// Helpers
// ---------------------------------------------------------------------------
__device__ __forceinline__ uint32_t smem_u32(const void* p) {
    uint32_t a;
    asm("{ .reg .u64 t; cvta.to.shared.u64 t, %1; cvt.u32.u64 %0, t; }"
        : "=r"(a) : "l"(p));
    return a;
}
__device__ __forceinline__ void cpa16(uint32_t dst, const void* src) {
    asm volatile("cp.async.cg.shared.global [%0], [%1], 16;"
                 :: "r"(dst), "l"(src));
}
// round fp32 -> tf32 (result is fp32 bits with low 13 mantissa bits zero)
__device__ __forceinline__ float tf32r(float x) {
    uint32_t r;
    asm("cvt.rna.tf32.f32 %0, %1;" : "=r"(r) : "f"(x));
    return __uint_as_float(r);
}
__device__ __forceinline__ void mma_tf32_16x8x8(float c[4],
                                                const uint32_t a[4],
                                                const uint32_t b[2]) {
    asm volatile(
        "mma.sync.aligned.m16n8k8.row.col.f32.tf32.tf32.f32 "
        "{%0,%1,%2,%3}, {%4,%5,%6,%7}, {%8,%9}, {%0,%1,%2,%3};"
        : "+f"(c[0]), "+f"(c[1]), "+f"(c[2]), "+f"(c[3])
        : "r"(a[0]), "r"(a[1]), "r"(a[2]), "r"(a[3]),
          "r"(b[0]), "r"(b[1]));
}

// ---------------------------------------------------------------------------
// Batched tf32 rounding (one kernel for x + all weight matrices)
// ---------------------------------------------------------------------------
struct RoundJob  { const float* src; float* dst; int n4; };
struct RoundJobs { RoundJob j[7]; };

__global__ void round_all(RoundJobs jobs)
{
    const RoundJob J = jobs.j[blockIdx.y];
    for (int i = blockIdx.x * blockDim.x + threadIdx.x; i < J.n4;
         i += gridDim.x * blockDim.x) {
        float4 a = ((const float4*)J.src)[i];
        a.x = tf32r(a.x); a.y = tf32r(a.y);
        a.z = tf32r(a.z); a.w = tf32r(a.w);
        ((float4*)J.dst)[i] = a;
    }
}

// ---------------------------------------------------------------------------
// tf32 mma.sync GEMM:  C[m,n] = sum_k A[m,k] * W[n,k]  (+bias, +epilogue)
// A and W MUST already be tf32-rounded — fragments are fed as raw bits.
// 512 threads / 16 warps (4x4), block 128x(NT*32), warp tile 32x(NT*8).
// Small accumulators (32 regs) -> <=64 regs -> 32 warps/SM (50% occ).
// BK = 32 per stage, 2 smem stages; final-iteration wait_group 0 closes
// the empty-group hazard.
// ACT: 0 identity  1 softplus  2 u-gate  3 v-add
//      4 merged gates: cols < H_ -> u-gate(W,bias,C), else v-add(W2,bias2,C2)
// KSPLIT > 1: blockIdx.x selects a K-chunk, n0 = 0, C += bx * M_ * ldc.
// ---------------------------------------------------------------------------
template<int ACT, int NT, int KSPLIT>
__global__ __launch_bounds__(512, 2)
void mma_gemm(const float* __restrict__ A, int lda,
              const float* __restrict__ W, int ldw,
              const float* __restrict__ bias,
              const float* __restrict__ EX,
              float* __restrict__ C, int ldc, int K,
              const float* __restrict__ W2,
              const float* __restrict__ bias2,
              float* __restrict__ C2)
{
    constexpr int BN   = NT * 32;            // 128 or 64
    constexpr int LDSM = 36;                 // padded row stride (floats)
    constexpr int BCH  = (BN * 32) / (512 * 4);   // B float4 chunks / thread
    extern __shared__ float sm[];
    float* Asm = sm;                          // [2][128][36]
    float* Bsm = sm + 2 * 128 * LDSM;         // [2][BN ][36]

    const int tid  = threadIdx.x;
    const int warp = tid >> 5, lane = tid & 31;
    const int gid  = lane >> 2, tig = lane & 3;
    const int wm   = warp & 3,  wn  = warp >> 2;
    const int m0   = blockIdx.y * 128;

    int n0, koff, keff;
    if (KSPLIT > 1) {
        n0   = 0;
        keff = K / KSPLIT;
        koff = blockIdx.x * keff;
        C   += (size_t)blockIdx.x * M_ * ldc;
    } else {
        n0   = blockIdx.x * BN;
        keff = K;
        koff = 0;
    }

    // merged-gate column split
    bool upper = false;
    const float* Wuse = W;
    const float* buse = bias;
    float*       Cuse = C;
    int n0w = n0;
    if (ACT == 4 && n0 >= H_) {
        upper = true; Wuse = W2; buse = bias2; Cuse = C2; n0w = n0 - H_;
    }

    const int mbase = wm * 32;
    const int nbase = wn * (NT * 8);

    auto sA = [&](int st, int row, int col) -> float* {
        return Asm + (st * 128 + row) * LDSM
                   + ((col + ((row >> 3) & 1) * 16) & 31);
    };
    auto sB = [&](int st, int row, int col) -> float* {
        return Bsm + (st * BN + row) * LDSM
                   + ((col + ((row >> 3) & 1) * 16) & 31);
    };

    float c[2][NT][4];
    #pragma unroll
    for (int i = 0; i < 2; i++)
        #pragma unroll
        for (int j = 0; j < NT; j++)
            #pragma unroll
            for (int q = 0; q < 4; q++) c[i][j][q] = 0.f;

    // gmem -> smem load slots
    const int ar  = tid >> 2;                 // 0..127
    const int acb = (tid & 3) * 8;            // 2 float4s per thread (A)
    const int br  = (BN == 128) ? (tid >> 2) : (tid >> 3);
    const int bcb = (BN == 128) ? (tid & 3) * 8 : (tid & 7) * 4;
    const float* aq = A + (size_t)(m0 + ar) * lda + koff + acb;
    const float* bq = Wuse + (size_t)(n0w + br) * ldw + koff + bcb;

    uint32_t adst[2][2], bdst[2][BCH];
    #pragma unroll
    for (int st = 0; st < 2; st++) {
        #pragma unroll
        for (int c0 = 0; c0 < 2; c0++)
            adst[st][c0] = smem_u32(sA(st, ar, acb + 4 * c0));
        #pragma unroll
        for (int c0 = 0; c0 < BCH; c0++)
            bdst[st][c0] = smem_u32(sB(st, br, bcb + 4 * c0));
    }

    const int nk = keff >> 5;               // stages of BK=32

    auto issue_stage = [&](int t) {
        if (t < nk) {
            const int sb = t & 1;
            #pragma unroll
            for (int c0 = 0; c0 < 2; c0++)
                cpa16(adst[sb][c0], aq + (size_t)t * 32 + 4 * c0);
            #pragma unroll
            for (int c0 = 0; c0 < BCH; c0++)
                cpa16(bdst[sb][c0], bq + (size_t)t * 32 + 4 * c0);
        }
        asm volatile("cp.async.commit_group;" ::: "memory");
    };

    issue_stage(0);
    issue_stage(1);

    for (int kt = 0; kt < nk; ++kt) {
        if (kt < nk - 1)
            asm volatile("cp.async.wait_group 1;" ::: "memory");
        else
            asm volatile("cp.async.wait_group 0;" ::: "memory");
        __syncthreads();
        const int st = kt & 1;

        #pragma unroll
        for (int ks = 0; ks < 4; ks++) {
            uint32_t af[2][4], bf[NT][2];
            #pragma unroll
            for (int ti = 0; ti < 2; ti++) {
                const int m = mbase + 16 * ti + gid;
                af[ti][0] = __float_as_uint(*sA(st, m,     ks * 8 + tig));
                af[ti][1] = __float_as_uint(*sA(st, m + 8, ks * 8 + tig));
                af[ti][2] = __float_as_uint(*sA(st, m,     ks * 8 + tig + 4));
                af[ti][3] = __float_as_uint(*sA(st, m + 8, ks * 8 + tig + 4));
            }
            #pragma unroll
            for (int tj = 0; tj < NT; tj++) {
                const int n = nbase + 8 * tj + gid;
                bf[tj][0] = __float_as_uint(*sB(st, n, ks * 8 + tig));
                bf[tj][1] = __float_as_uint(*sB(st, n, ks * 8 + tig + 4));
            }
            #pragma unroll
            for (int ti = 0; ti < 2; ti++)
                #pragma unroll
                for (int tj = 0; tj < NT; tj++)
                    mma_tf32_16x8x8(c[ti][tj], af[ti], bf[tj]);
        }

        __syncthreads();                 // all reads of stage st done
        issue_stage(kt + 2);             // safe to overwrite buffer st
    }

    // epilogue
    #pragma unroll
    for (int ti = 0; ti < 2; ti++) {
        #pragma unroll
        for (int half = 0; half < 2; half++) {
            const int row = m0 + mbase + 16 * ti + gid + half * 8;
            #pragma unroll
            for (int tj = 0; tj < NT; tj++) {
                const int col = n0w + nbase + 8 * tj + 2 * tig;
                float v0 = c[ti][tj][half * 2 + 0];
                float v1 = c[ti][tj][half * 2 + 1];
                if (bias) { v0 += buse[col]; v1 += buse[col + 1]; }
                if (ACT == 1) {
                    v0 = (v0 > 20.f) ? v0 : log1pf(__expf(v0));
                    v1 = (v1 > 20.f) ? v1 : log1pf(__expf(v1));
                } else if (ACT == 2 || (ACT == 4 && !upper)) {
                    const float z10 = EX[(size_t)row * H2_ + col];
                    const float z11 = EX[(size_t)row * H2_ + col + 1];
                    v0 = z10 * (1.f + 1.f / (1.f + __expf(-v0)));
                    v1 = z11 * (1.f + 1.f / (1.f + __expf(-v1)));
                } else if (ACT == 3 || (ACT == 4 && upper)) {
                    v0 += EX[(size_t)row * H2_ + H_ + col];
                    v1 += EX[(size_t)row * H2_ + H_ + col + 1];
                }
                float2 r; r.x = v0; r.y = v1;
                *(float2*)(Cuse + (size_t)row * ldc + col) = r;
            }
        }
    }
}

constexpr int SMEM_NT4 = (2 * 128 * 36 + 2 * 128 * 36) * 4;   // 73728
constexpr int SMEM_NT2 = (2 * 128 * 36 + 2 * 64  * 36) * 4;   // 55296

// ---------------------------------------------------------------------------
// Reduce split-K partials; output rounded to tf32 (feeds the dt GEMM)
// ---------------------------------------------------------------------------
__global__ void zc_reduce(const float* __restrict__ zp,
                          float* __restrict__ zc)
{
    const int idx = blockIdx.x * blockDim.x + threadIdx.x;   // float4 index
    if (idx >= M_ * 64 / 4) return;
    const float4* p0 = (const float4*)zp + idx;
    float4 a = p0[0];
    #pragma unroll
    for (int j = 1; j < KSP_; j++) {
        const float4 bq = p0[(size_t)j * (M_ * 64 / 4)];
        a.x += bq.x; a.y += bq.y; a.z += bq.z; a.w += bq.w;
    }
    a.x = tf32r(a.x); a.y = tf32r(a.y); a.z = tf32r(a.z); a.w = tf32r(a.w);
    ((float4*)zc)[idx] = a;
}

// ---------------------------------------------------------------------------
// LayerNorm over D=512, one block (256 threads) per token.
// ---------------------------------------------------------------------------
__global__ void ln_kernel(const float* __restrict__ ctx,
                          const float* __restrict__ w,
                          const float* __restrict__ b,
                          float* __restrict__ out)
{
    __shared__ float red[32];
    const int m = blockIdx.x;
    const int t = threadIdx.x;
    const float* xr = ctx + (size_t)m * D_;
    float v0 = xr[t], v1 = xr[t + 256];

    float s = v0 + v1;
    #pragma unroll
    for (int o = 16; o; o >>= 1) s += __shfl_xor_sync(0xffffffffu, s, o);
    if ((t & 31) == 0) red[t >> 5] = s;
    __syncthreads();
    if (t < 32) {
        float r = (t < 8) ? red[t] : 0.f;
        #pragma unroll
        for (int o = 4; o; o >>= 1) r += __shfl_xor_sync(0xffffffffu, r, o);
        if (t == 0) red[0] = r;
    }
    __syncthreads();
    const float mu = red[0] * (1.f / D_);
    const float d0 = v0 - mu, d1 = v1 - mu;

    float sq = d0 * d0 + d1 * d1;
    #pragma unroll
    for (int o = 16; o; o >>= 1) sq += __shfl_xor_sync(0xffffffffu, sq, o);
    __syncthreads();
    if ((t & 31) == 0) red[t >> 5] = sq;
    __syncthreads();
    if (t < 32) {
        float r = (t < 8) ? red[t] : 0.f;
        #pragma unroll
        for (int o = 4; o; o >>= 1) r += __shfl_xor_sync(0xffffffffu, r, o);
        if (t == 0) red[0] = r;
    }
    __syncthreads();
    const float inv = rsqrtf(red[0] * (1.f / D_) + 1e-5f);

    float* orow = out + (size_t)m * D_;
    orow[t]       = tf32r(d0 * inv * w[t]       + b[t]);
    orow[t + 256] = tf32r(d1 * inv * w[t + 256] + b[t + 256]);
}

// ---------------------------------------------------------------------------
// Causal depthwise conv3 + SiLU (float4-vectorized).
// ---------------------------------------------------------------------------
__global__ void conv_kernel(const float* __restrict__ u,
                            const float* __restrict__ cw,
                            const float* __restrict__ cb,
                            float* __restrict__ uc)
{
    const size_t i4 = (size_t)blockIdx.x * blockDim.x + threadIdx.x;
    if (i4 >= (size_t)M_ * H_ / 4) return;
    const size_t idx = i4 * 4;
    const int    h = (int)(idx % H_);
    const size_t m = idx / H_;
    const int    l = (int)(m % L_);

    const float4 x0  = *(const float4*)(u + idx);
    float4 xm1 = make_float4(0.f, 0.f, 0.f, 0.f);
    float4 xm2 = make_float4(0.f, 0.f, 0.f, 0.f);
    if (l >= 1) xm1 = *(const float4*)(u + idx - H_);
    if (l >= 2) xm2 = *(const float4*)(u + idx - 2 * H_);

    const float* x0p  = (const float*)&x0;
    const float* xm1p = (const float*)&xm1;
    const float* xm2p = (const float*)&xm2;
    float4 o;
    float* op = (float*)&o;
    #pragma unroll
    for (int q = 0; q < 4; q++) {
        const float r = cw[(h + q) * 3 + 0] * xm2p[q]
                      + cw[(h + q) * 3 + 1] * xm1p[q]
                      + cw[(h + q) * 3 + 2] * x0p[q] + cb[h + q];
        op[q] = tf32r(r / (1.f + __expf(-r)));   // silu, tf32-rounded
    }
    *(float4*)(uc + idx) = o;
}

// ---------------------------------------------------------------------------
// Selective scan, chunked (16 steps per chunk).
// ---------------------------------------------------------------------------
__global__ void scan_kernel(const float* __restrict__ uc,
                            const float* __restrict__ dt,
                            const float* __restrict__ zc,
                            const float* __restrict__ v,
                            const float* __restrict__ f_log,
                            const float* __restrict__ g,
                            float* __restrict__ yv)
{
    const int wid  = (int)((blockIdx.x * blockDim.x + threadIdx.x) >> 5);
    const int lane = threadIdx.x & 31;
    if (wid >= B_ * H_ / 2) return;
    const int b  = wid / (H_ / 2);
    const int h0 = (wid % (H_ / 2)) * 2;
    const int hl = lane >> 4;
    const int s  = lane & 15;
    const int h  = h0 + hl;

    const float a_hs = -__expf(f_log[h * S_ + s]);
    const float gd   = g[h];
    const float* zcb  = zc + (size_t)b * L_ * 64;
    const size_t baseH = (size_t)b * L_ * H_ + h;

    float bc0[16], dt0, uc0, vv0, du0;
    {
        #pragma unroll
        for (int j = 0; j < 16; j++)
            bc0[j] = zcb[(size_t)j * 64 + 32 + lane];
        const size_t o = baseH + (size_t)s * H_;
        dt0 = dt[o]; uc0 = uc[o]; vv0 = v[o];
        du0 = dt0 * uc0;
    }

    float x = 0.f;

    for (int l0 = 0; l0 < L_; l0 += 16) {
        float bc1[16], dt1, uc1, vv1, du1;
        if (l0 + 16 < L_) {
            #pragma unroll
            for (int j = 0; j < 16; j++)
                bc1[j] = zcb[(size_t)(l0 + 16 + j) * 64 + 32 + lane];
            const size_t o = baseH + (size_t)(l0 + 16 + s) * H_;
            dt1 = dt[o]; uc1 = uc[o]; vv1 = v[o];
            du1 = dt1 * uc1;
        } else { dt1 = uc1 = vv1 = du1 = 0.f; }

        float prod[16];
        #pragma unroll
        for (int j = 0; j < 16; j++) {
            const float dtq = __shfl_sync(0xffffffffu, dt0, hl * 16 + j);
            const float duq = __shfl_sync(0xffffffffu, du0, hl * 16 + j);
            const float bm  = __shfl_sync(0xffffffffu, bc0[j], s);
            const float cm  = __shfl_sync(0xffffffffu, bc0[j], 16 + s);

            const float aa = __expf(dtq * a_hs);
            x = fmaf(aa, x, duq * bm);
            prod[j] = x * cm;
        }

        #pragma unroll
        for (int off = 8; off >= 1; off >>= 1) {
            #pragma unroll
            for (int j = 0; j < off; j++) {
                const float a = prod[j], bq = prod[j + off];
                const float send = (s & off) ? a : bq;
                const float t = __shfl_xor_sync(0xffffffffu, send, off);
                prod[j] = (s & off) ? (bq + t) : (a + t);
            }
        }

        const float sv = vv0 / (1.f + __expf(-vv0));
        yv[baseH + (size_t)(l0 + s) * H_] = tf32r((prod[0] + uc0 * gd) * sv);

        #pragma unroll
        for (int j = 0; j < 16; j++) bc0[j] = bc1[j];
        dt0 = dt1; uc0 = uc1; vv0 = vv1; du0 = du1;
    }
}

// ---------------------------------------------------------------------------
// Launch
// ---------------------------------------------------------------------------
extern "C" void kernel_launch(void* const* d_in, const int* in_sizes, int n_in,
                              void* d_out, int out_size)
{
    const float* x      = (const float*)d_in[0];
    const float* ctx    = (const float*)d_in[1];
    const float* Wa     = (const float*)d_in[2];
    const float* ba     = (const float*)d_in[3];
    const float* conv_w = (const float*)d_in[4];
    const float* conv_b = (const float*)d_in[5];
    const float* Wc     = (const float*)d_in[6];
    const float* We     = (const float*)d_in[7];
    const float* be     = (const float*)d_in[8];
    const float* f_log  = (const float*)d_in[9];
    const float* g      = (const float*)d_in[10];
    const float* Wi     = (const float*)d_in[11];
    const float* bi     = (const float*)d_in[12];
    const float* ln_w   = (const float*)d_in[13];
    const float* ln_b   = (const float*)d_in[14];
    const float* Wgb    = (const float*)d_in[15];
    const float* bgb    = (const float*)d_in[16];
    const float* Wgc    = (const float*)d_in[17];
    const float* bgc    = (const float*)d_in[18];
    float* out = (float*)d_out;

    float *cln, *z, *u, *v, *uc, *zcp, *zcb, *dtb, *yv;
    float *xr, *wa, *wgb, *wgc, *wc, *we, *wi;
    cudaGetSymbolAddress((void**)&cln, g_cln);
    cudaGetSymbolAddress((void**)&z,   g_z);
    cudaGetSymbolAddress((void**)&u,   g_u);
    cudaGetSymbolAddress((void**)&v,   g_v);
    cudaGetSymbolAddress((void**)&uc,  g_uc);
    cudaGetSymbolAddress((void**)&zcp, g_zcp);
    cudaGetSymbolAddress((void**)&zcb, g_zc);
    cudaGetSymbolAddress((void**)&dtb, g_dt);
    cudaGetSymbolAddress((void**)&yv,  g_yv);
    cudaGetSymbolAddress((void**)&xr,  g_xr);
    cudaGetSymbolAddress((void**)&wa,  g_wa);
    cudaGetSymbolAddress((void**)&wgb, g_wgb);
    cudaGetSymbolAddress((void**)&wgc, g_wgc);
    cudaGetSymbolAddress((void**)&wc,  g_wc);
    cudaGetSymbolAddress((void**)&we,  g_we);
    cudaGetSymbolAddress((void**)&wi,  g_wi);

    cudaFuncSetAttribute(mma_gemm<0,4,1>,
        cudaFuncAttributeMaxDynamicSharedMemorySize, SMEM_NT4);
    cudaFuncSetAttribute(mma_gemm<1,4,1>,
        cudaFuncAttributeMaxDynamicSharedMemorySize, SMEM_NT4);
    cudaFuncSetAttribute(mma_gemm<4,4,1>,
        cudaFuncAttributeMaxDynamicSharedMemorySize, SMEM_NT4);
    cudaFuncSetAttribute(mma_gemm<0,2,KSP_>,
        cudaFuncAttributeMaxDynamicSharedMemorySize, SMEM_NT2);

    // 0. tf32-round x and all weight matrices (one batched kernel)
    RoundJobs rj;
    rj.j[0] = { x,   xr,  M_ * D_   / 4 };
    rj.j[1] = { Wa,  wa,  H2_ * D_  / 4 };
    rj.j[2] = { Wgb, wgb, H_ * D_   / 4 };
    rj.j[3] = { Wgc, wgc, H_ * D_   / 4 };
    rj.j[4] = { Wc,  wc,  64 * H_   / 4 };
    rj.j[5] = { We,  we,  H_ * 32   / 4 };
    rj.j[6] = { Wi,  wi,  D_ * H_   / 4 };
    round_all<<<dim3(1024, 7), 256>>>(rj);

    // 1. LayerNorm(ctx)
    ln_kernel<<<M_, 256>>>(ctx, ln_w, ln_b, cln);

    // 2. z = x @ Wa^T + ba                      [8192, 2048]
    mma_gemm<0,4,1><<<dim3(H2_ / 128, M_ / 128), 512, SMEM_NT4>>>(
        xr, D_, wa, D_, ba, nullptr, z, H2_, D_,
        nullptr, nullptr, nullptr);

    // 3+4. merged gate GEMM: u (cols<H) and v (cols>=H) in one launch
    mma_gemm<4,4,1><<<dim3(H2_ / 128, M_ / 128), 512, SMEM_NT4>>>(
        cln, D_, wgb, D_, bgb, z, u, H_, D_,
        wgc, bgc, v);

    // 5. uc = silu(causal depthwise conv3(u))
    conv_kernel<<<(int)(((size_t)M_ * H_ / 4 + 255) / 256), 256>>>(
        u, conv_w, conv_b, uc);

    // 6. zc = uc @ Wc^T  (split-K over 4 chunks, then reduce w/ tf32 round)
    mma_gemm<0,2,KSP_><<<dim3(KSP_, M_ / 128), 512, SMEM_NT2>>>(
        uc, H_, wc, H_, nullptr, nullptr, zcp, 64, H_,
        nullptr, nullptr, nullptr);
    zc_reduce<<<(M_ * 64 / 4 + 255) / 256, 256>>>(zcp, zcb);

    // 7. dt = softplus(zc[:, :R] @ We^T + be)   [8192, 1024]
    mma_gemm<1,4,1><<<dim3(H_ / 128, M_ / 128), 512, SMEM_NT4>>>(
        zcb, 64, we, 32, be, nullptr, dtb, H_, 32,
        nullptr, nullptr, nullptr);

    // 8. selective scan (fused skip + silu(v) gate)
    scan_kernel<<<(B_ * H_ / 2) / 8, 256>>>(uc, dtb, zcb, v, f_log, g, yv);

    // 9. out = yv @ Wi^T + bi                   [8192, 512]
    mma_gemm<0,4,1><<<dim3(D_ / 128, M_ / 128), 512, SMEM_NT4>>>(
        yv, H_, wi, H_, bi, nullptr, out, D_, H_,
        nullptr, nullptr, nullptr);
}

// round 9
// speedup vs baseline: 1.1439x; 1.0071x over previous
#include <cuda_runtime.h>
#include <cstdint>
#include <math.h>

// ---------------------------------------------------------------------------
// Problem constants
// ---------------------------------------------------------------------------
constexpr int B_  = 4;
constexpr int L_  = 2048;
constexpr int D_  = 512;
constexpr int H_  = 1024;   // 2*D
constexpr int S_  = 16;
constexpr int M_  = B_ * L_;        // 8192 tokens
constexpr int H2_ = 2 * H_;         // 2048
constexpr int KSP_ = 4;             // split-K factor for the zc GEMM

// ---------------------------------------------------------------------------
// Scratch (device globals; no allocation allowed)
// ---------------------------------------------------------------------------
__device__ float g_cln[M_ * D_];
__device__ float g_z  [M_ * H2_];
__device__ float g_p  [M_ * H_];    // gate pre-activation (raw)
__device__ float g_v  [M_ * H_];    // q, then v in-place
__device__ float g_uc [M_ * H_];
__device__ float g_zcp[KSP_ * M_ * 64];   // split-K partials
__device__ float g_zc [M_ * 64];
__device__ float g_dt [M_ * H_];
__device__ float g_yv [M_ * H_];
// tf32-rounded copies of inputs that feed GEMMs
__device__ float g_xr [M_ * D_];
__device__ float g_wa [H2_ * D_];
__device__ float g_wgb[H_ * D_];
__device__ float g_wgc[H_ * D_];
__device__ float g_wc [64 * H_];
__device__ float g_we [H_ * 32];
__device__ float g_wi [D_ * H_];

// ---------------------------------------------------------------------------
// Helpers
// ---------------------------------------------------------------------------
__device__ __forceinline__ uint32_t smem_u32(const void* p) {
    uint32_t a;
    asm("{ .reg .u64 t; cvta.to.shared.u64 t, %1; cvt.u32.u64 %0, t; }"
        : "=r"(a) : "l"(p));
    return a;
}
__device__ __forceinline__ void cpa16(uint32_t dst, const void* src) {
    asm volatile("cp.async.cg.shared.global [%0], [%1], 16;"
                 :: "r"(dst), "l"(src));
}
// round fp32 -> tf32 (result is fp32 bits with low 13 mantissa bits zero)
__device__ __forceinline__ float tf32r(float x) {
    uint32_t r;
    asm("cvt.rna.tf32.f32 %0, %1;" : "=r"(r) : "f"(x));
    return __uint_as_float(r);
}
__device__ __forceinline__ void mma_tf32_16x8x8(float c[4],
                                                const uint32_t a[4],
                                                const uint32_t b[2]) {
    asm volatile(
        "mma.sync.aligned.m16n8k8.row.col.f32.tf32.tf32.f32 "
        "{%0,%1,%2,%3}, {%4,%5,%6,%7}, {%8,%9}, {%0,%1,%2,%3};"
        : "+f"(c[0]), "+f"(c[1]), "+f"(c[2]), "+f"(c[3])
        : "r"(a[0]), "r"(a[1]), "r"(a[2]), "r"(a[3]),
          "r"(b[0]), "r"(b[1]));
}

// ---------------------------------------------------------------------------
// Batched tf32 rounding (one kernel for x + all weight matrices)
// ---------------------------------------------------------------------------
struct RoundJob  { const float* src; float* dst; int n4; };
struct RoundJobs { RoundJob j[7]; };

__global__ void round_all(RoundJobs jobs)
{
    const RoundJob J = jobs.j[blockIdx.y];
    for (int i = blockIdx.x * blockDim.x + threadIdx.x; i < J.n4;
         i += gridDim.x * blockDim.x) {
        float4 a = ((const float4*)J.src)[i];
        a.x = tf32r(a.x); a.y = tf32r(a.y);
        a.z = tf32r(a.z); a.w = tf32r(a.w);
        ((float4*)J.dst)[i] = a;
    }
}

// ---------------------------------------------------------------------------
// tf32 mma.sync GEMM:  C[m,n] = sum_k A[m,k] * W[n,k]  (+bias, +epilogue)
// 512 threads / 16 warps (4x4), block 128x(NT*32), warp tile 32x(NT*8).
// BK = 32 per stage, 2 smem stages.
// ACT: 0 identity  1 softplus
//      5 dual plain: cols < H_ -> (W,bias)->C, cols >= H_ -> (W2,bias2)->C2
// KSPLIT > 1: blockIdx.x selects a K-chunk, n0 = 0, C += bx * M_ * ldc.
// ---------------------------------------------------------------------------
template<int ACT, int NT, int KSPLIT>
__global__ __launch_bounds__(512, 2)
void mma_gemm(const float* __restrict__ A, int lda,
              const float* __restrict__ W, int ldw,
              const float* __restrict__ bias,
              float* __restrict__ C, int ldc, int K,
              const float* __restrict__ W2,
              const float* __restrict__ bias2,
              float* __restrict__ C2)
{
    constexpr int BN   = NT * 32;            // 128 or 64
    constexpr int LDSM = 36;                 // padded row stride (floats)
    constexpr int BCH  = (BN * 32) / (512 * 4);   // B float4 chunks / thread
    extern __shared__ float sm[];
    float* Asm = sm;                          // [2][128][36]
    float* Bsm = sm + 2 * 128 * LDSM;         // [2][BN ][36]

    const int tid  = threadIdx.x;
    const int warp = tid >> 5, lane = tid & 31;
    const int gid  = lane >> 2, tig = lane & 3;
    const int wm   = warp & 3,  wn  = warp >> 2;
    const int m0   = blockIdx.y * 128;

    int n0, koff, keff;
    if (KSPLIT > 1) {
        n0   = 0;
        keff = K / KSPLIT;
        koff = blockIdx.x * keff;
        C   += (size_t)blockIdx.x * M_ * ldc;
    } else {
        n0   = blockIdx.x * BN;
        keff = K;
        koff = 0;
    }

    // dual-output column split
    const float* Wuse = W;
    const float* buse = bias;
    float*       Cuse = C;
    int n0w = n0;
    if (ACT == 5 && n0 >= H_) {
        Wuse = W2; buse = bias2; Cuse = C2; n0w = n0 - H_;
    }

    const int mbase = wm * 32;
    const int nbase = wn * (NT * 8);

    auto sA = [&](int st, int row, int col) -> float* {
        return Asm + (st * 128 + row) * LDSM
                   + ((col + ((row >> 3) & 1) * 16) & 31);
    };
    auto sB = [&](int st, int row, int col) -> float* {
        return Bsm + (st * BN + row) * LDSM
                   + ((col + ((row >> 3) & 1) * 16) & 31);
    };

    float c[2][NT][4];
    #pragma unroll
    for (int i = 0; i < 2; i++)
        #pragma unroll
        for (int j = 0; j < NT; j++)
            #pragma unroll
            for (int q = 0; q < 4; q++) c[i][j][q] = 0.f;

    // gmem -> smem load slots
    const int ar  = tid >> 2;                 // 0..127
    const int acb = (tid & 3) * 8;            // 2 float4s per thread (A)
    const int br  = (BN == 128) ? (tid >> 2) : (tid >> 3);
    const int bcb = (BN == 128) ? (tid & 3) * 8 : (tid & 7) * 4;
    const float* aq = A + (size_t)(m0 + ar) * lda + koff + acb;
    const float* bq = Wuse + (size_t)(n0w + br) * ldw + koff + bcb;

    uint32_t adst[2][2], bdst[2][BCH];
    #pragma unroll
    for (int st = 0; st < 2; st++) {
        #pragma unroll
        for (int c0 = 0; c0 < 2; c0++)
            adst[st][c0] = smem_u32(sA(st, ar, acb + 4 * c0));
        #pragma unroll
        for (int c0 = 0; c0 < BCH; c0++)
            bdst[st][c0] = smem_u32(sB(st, br, bcb + 4 * c0));
    }

    const int nk = keff >> 5;               // stages of BK=32

    auto issue_stage = [&](int t) {
        if (t < nk) {
            const int sb = t & 1;
            #pragma unroll
            for (int c0 = 0; c0 < 2; c0++)
                cpa16(adst[sb][c0], aq + (size_t)t * 32 + 4 * c0);
            #pragma unroll
            for (int c0 = 0; c0 < BCH; c0++)
                cpa16(bdst[sb][c0], bq + (size_t)t * 32 + 4 * c0);
        }
        asm volatile("cp.async.commit_group;" ::: "memory");
    };

    issue_stage(0);
    issue_stage(1);

    for (int kt = 0; kt < nk; ++kt) {
        if (kt < nk - 1)
            asm volatile("cp.async.wait_group 1;" ::: "memory");
        else
            asm volatile("cp.async.wait_group 0;" ::: "memory");
        __syncthreads();
        const int st = kt & 1;

        #pragma unroll
        for (int ks = 0; ks < 4; ks++) {
            uint32_t af[2][4], bf[NT][2];
            #pragma unroll
            for (int ti = 0; ti < 2; ti++) {
                const int m = mbase + 16 * ti + gid;
                af[ti][0] = __float_as_uint(*sA(st, m,     ks * 8 + tig));
                af[ti][1] = __float_as_uint(*sA(st, m + 8, ks * 8 + tig));
                af[ti][2] = __float_as_uint(*sA(st, m,     ks * 8 + tig + 4));
                af[ti][3] = __float_as_uint(*sA(st, m + 8, ks * 8 + tig + 4));
            }
            #pragma unroll
            for (int tj = 0; tj < NT; tj++) {
                const int n = nbase + 8 * tj + gid;
                bf[tj][0] = __float_as_uint(*sB(st, n, ks * 8 + tig));
                bf[tj][1] = __float_as_uint(*sB(st, n, ks * 8 + tig + 4));
            }
            #pragma unroll
            for (int ti = 0; ti < 2; ti++)
                #pragma unroll
                for (int tj = 0; tj < NT; tj++)
                    mma_tf32_16x8x8(c[ti][tj], af[ti], bf[tj]);
        }

        __syncthreads();                 // all reads of stage st done
        issue_stage(kt + 2);             // safe to overwrite buffer st
    }

    // epilogue
    #pragma unroll
    for (int ti = 0; ti < 2; ti++) {
        #pragma unroll
        for (int half = 0; half < 2; half++) {
            const int row = m0 + mbase + 16 * ti + gid + half * 8;
            #pragma unroll
            for (int tj = 0; tj < NT; tj++) {
                const int col = n0w + nbase + 8 * tj + 2 * tig;
                float v0 = c[ti][tj][half * 2 + 0];
                float v1 = c[ti][tj][half * 2 + 1];
                if (bias) { v0 += buse[col]; v1 += buse[col + 1]; }
                if (ACT == 1) {
                    v0 = (v0 > 20.f) ? v0 : log1pf(__expf(v0));
                    v1 = (v1 > 20.f) ? v1 : log1pf(__expf(v1));
                }
                float2 r; r.x = v0; r.y = v1;
                *(float2*)(Cuse + (size_t)row * ldc + col) = r;
            }
        }
    }
}

constexpr int SMEM_NT4 = (2 * 128 * 36 + 2 * 128 * 36) * 4;   // 73728
constexpr int SMEM_NT2 = (2 * 128 * 36 + 2 * 64  * 36) * 4;   // 55296

// ---------------------------------------------------------------------------
// Reduce split-K partials; output rounded to tf32 (feeds the dt GEMM)
// ---------------------------------------------------------------------------
__global__ void zc_reduce(const float* __restrict__ zp,
                          float* __restrict__ zc)
{
    const int idx = blockIdx.x * blockDim.x + threadIdx.x;   // float4 index
    if (idx >= M_ * 64 / 4) return;
    const float4* p0 = (const float4*)zp + idx;
    float4 a = p0[0];
    #pragma unroll
    for (int j = 1; j < KSP_; j++) {
        const float4 bq = p0[(size_t)j * (M_ * 64 / 4)];
        a.x += bq.x; a.y += bq.y; a.z += bq.z; a.w += bq.w;
    }
    a.x = tf32r(a.x); a.y = tf32r(a.y); a.z = tf32r(a.z); a.w = tf32r(a.w);
    ((float4*)zc)[idx] = a;
}

// ---------------------------------------------------------------------------
// LayerNorm over D=512, one block (256 threads) per token.
// ---------------------------------------------------------------------------
__global__ void ln_kernel(const float* __restrict__ ctx,
                          const float* __restrict__ w,
                          const float* __restrict__ b,
                          float* __restrict__ out)
{
    __shared__ float red[32];
    const int m = blockIdx.x;
    const int t = threadIdx.x;
    const float* xr = ctx + (size_t)m * D_;
    float v0 = xr[t], v1 = xr[t + 256];

    float s = v0 + v1;
    #pragma unroll
    for (int o = 16; o; o >>= 1) s += __shfl_xor_sync(0xffffffffu, s, o);
    if ((t & 31) == 0) red[t >> 5] = s;
    __syncthreads();
    if (t < 32) {
        float r = (t < 8) ? red[t] : 0.f;
        #pragma unroll
        for (int o = 4; o; o >>= 1) r += __shfl_xor_sync(0xffffffffu, r, o);
        if (t == 0) red[0] = r;
    }
    __syncthreads();
    const float mu = red[0] * (1.f / D_);
    const float d0 = v0 - mu, d1 = v1 - mu;

    float sq = d0 * d0 + d1 * d1;
    #pragma unroll
    for (int o = 16; o; o >>= 1) sq += __shfl_xor_sync(0xffffffffu, sq, o);
    __syncthreads();
    if ((t & 31) == 0) red[t >> 5] = sq;
    __syncthreads();
    if (t < 32) {
        float r = (t < 8) ? red[t] : 0.f;
        #pragma unroll
        for (int o = 4; o; o >>= 1) r += __shfl_xor_sync(0xffffffffu, r, o);
        if (t == 0) red[0] = r;
    }
    __syncthreads();
    const float inv = rsqrtf(red[0] * (1.f / D_) + 1e-5f);

    float* orow = out + (size_t)m * D_;
    orow[t]       = tf32r(d0 * inv * w[t]       + b[t]);
    orow[t + 256] = tf32r(d1 * inv * w[t + 256] + b[t + 256]);
}

// ---------------------------------------------------------------------------
// Fused uv + causal depthwise conv3 + SiLU.
// Recomputes u = z1*(1+sigmoid(p)) at the 3 conv taps in registers,
// writes uc = tf32(silu(conv(u))) and v = z2 + q (in-place over q).
// ---------------------------------------------------------------------------
__global__ void uvconv_kernel(const float* __restrict__ Z,
                              const float* __restrict__ P,
                              float* __restrict__ Q,     // becomes v
                              const float* __restrict__ cw,
                              const float* __restrict__ cb,
                              float* __restrict__ uc)
{
    const size_t i4 = (size_t)blockIdx.x * blockDim.x + threadIdx.x;
    if (i4 >= (size_t)M_ * H_ / 4) return;
    const size_t idx = i4 * 4;
    const int    h = (int)(idx % H_);
    const size_t m = idx / H_;
    const int    l = (int)(m % L_);

    const size_t zi = m * H2_ + h;

    float4 u0, u1, u2;
    {
        const float4 p0 = *(const float4*)(P + idx);
        const float4 z0 = *(const float4*)(Z + zi);
        float* up = (float*)&u0; const float* pp = (const float*)&p0;
        const float* zp = (const float*)&z0;
        #pragma unroll
        for (int q = 0; q < 4; q++)
            up[q] = zp[q] * (1.f + 1.f / (1.f + __expf(-pp[q])));
    }
    if (l >= 1) {
        const float4 p1 = *(const float4*)(P + idx - H_);
        const float4 z1q = *(const float4*)(Z + zi - H2_);
        float* up = (float*)&u1; const float* pp = (const float*)&p1;
        const float* zp = (const float*)&z1q;
        #pragma unroll
        for (int q = 0; q < 4; q++)
            up[q] = zp[q] * (1.f + 1.f / (1.f + __expf(-pp[q])));
    } else u1 = make_float4(0.f, 0.f, 0.f, 0.f);
    if (l >= 2) {
        const float4 p2 = *(const float4*)(P + idx - 2 * H_);
        const float4 z2q = *(const float4*)(Z + zi - 2 * H2_);
        float* up = (float*)&u2; const float* pp = (const float*)&p2;
        const float* zp = (const float*)&z2q;
        #pragma unroll
        for (int q = 0; q < 4; q++)
            up[q] = zp[q] * (1.f + 1.f / (1.f + __expf(-pp[q])));
    } else u2 = make_float4(0.f, 0.f, 0.f, 0.f);

    const float* u0p = (const float*)&u0;
    const float* u1p = (const float*)&u1;
    const float* u2p = (const float*)&u2;
    float4 o; float* op = (float*)&o;
    #pragma unroll
    for (int q = 0; q < 4; q++) {
        const float r = cw[(h + q) * 3 + 0] * u2p[q]
                      + cw[(h + q) * 3 + 1] * u1p[q]
                      + cw[(h + q) * 3 + 2] * u0p[q] + cb[h + q];
        op[q] = tf32r(r / (1.f + __expf(-r)));   // silu, tf32-rounded
    }
    *(float4*)(uc + idx) = o;

    // v = z2 + q (in-place over q)
    {
        const float4 qv = *(const float4*)(Q + idx);
        const float4 z2v = *(const float4*)(Z + zi + H_);
        float4 vv;
        vv.x = qv.x + z2v.x; vv.y = qv.y + z2v.y;
        vv.z = qv.z + z2v.z; vv.w = qv.w + z2v.w;
        *(float4*)(Q + idx) = vv;
    }
}

// ---------------------------------------------------------------------------
// Selective scan, chunked (16 steps per chunk).
// ---------------------------------------------------------------------------
__global__ void scan_kernel(const float* __restrict__ uc,
                            const float* __restrict__ dt,
                            const float* __restrict__ zc,
                            const float* __restrict__ v,
                            const float* __restrict__ f_log,
                            const float* __restrict__ g,
                            float* __restrict__ yv)
{
    const int wid  = (int)((blockIdx.x * blockDim.x + threadIdx.x) >> 5);
    const int lane = threadIdx.x & 31;
    if (wid >= B_ * H_ / 2) return;
    const int b  = wid / (H_ / 2);
    const int h0 = (wid % (H_ / 2)) * 2;
    const int hl = lane >> 4;
    const int s  = lane & 15;
    const int h  = h0 + hl;

    const float a_hs = -__expf(f_log[h * S_ + s]);
    const float gd   = g[h];
    const float* zcb  = zc + (size_t)b * L_ * 64;
    const size_t baseH = (size_t)b * L_ * H_ + h;

    float bc0[16], dt0, uc0, vv0, du0;
    {
        #pragma unroll
        for (int j = 0; j < 16; j++)
            bc0[j] = zcb[(size_t)j * 64 + 32 + lane];
        const size_t o = baseH + (size_t)s * H_;
        dt0 = dt[o]; uc0 = uc[o]; vv0 = v[o];
        du0 = dt0 * uc0;
    }

    float x = 0.f;

    for (int l0 = 0; l0 < L_; l0 += 16) {
        float bc1[16], dt1, uc1, vv1, du1;
        if (l0 + 16 < L_) {
            #pragma unroll
            for (int j = 0; j < 16; j++)
                bc1[j] = zcb[(size_t)(l0 + 16 + j) * 64 + 32 + lane];
            const size_t o = baseH + (size_t)(l0 + 16 + s) * H_;
            dt1 = dt[o]; uc1 = uc[o]; vv1 = v[o];
            du1 = dt1 * uc1;
        } else { dt1 = uc1 = vv1 = du1 = 0.f; }

        float prod[16];
        #pragma unroll
        for (int j = 0; j < 16; j++) {
            const float dtq = __shfl_sync(0xffffffffu, dt0, hl * 16 + j);
            const float duq = __shfl_sync(0xffffffffu, du0, hl * 16 + j);
            const float bm  = __shfl_sync(0xffffffffu, bc0[j], s);
            const float cm  = __shfl_sync(0xffffffffu, bc0[j], 16 + s);

            const float aa = __expf(dtq * a_hs);
            x = fmaf(aa, x, duq * bm);
            prod[j] = x * cm;
        }

        #pragma unroll
        for (int off = 8; off >= 1; off >>= 1) {
            #pragma unroll
            for (int j = 0; j < off; j++) {
                const float a = prod[j], bq = prod[j + off];
                const float send = (s & off) ? a : bq;
                const float t = __shfl_xor_sync(0xffffffffu, send, off);
                prod[j] = (s & off) ? (bq + t) : (a + t);
            }
        }

        const float sv = vv0 / (1.f + __expf(-vv0));
        yv[baseH + (size_t)(l0 + s) * H_] = tf32r((prod[0] + uc0 * gd) * sv);

        #pragma unroll
        for (int j = 0; j < 16; j++) bc0[j] = bc1[j];
        dt0 = dt1; uc0 = uc1; vv0 = vv1; du0 = du1;
    }
}

// ---------------------------------------------------------------------------
// Launch
// ---------------------------------------------------------------------------
extern "C" void kernel_launch(void* const* d_in, const int* in_sizes, int n_in,
                              void* d_out, int out_size)
{
    const float* x      = (const float*)d_in[0];
    const float* ctx    = (const float*)d_in[1];
    const float* Wa     = (const float*)d_in[2];
    const float* ba     = (const float*)d_in[3];
    const float* conv_w = (const float*)d_in[4];
    const float* conv_b = (const float*)d_in[5];
    const float* Wc     = (const float*)d_in[6];
    const float* We     = (const float*)d_in[7];
    const float* be     = (const float*)d_in[8];
    const float* f_log  = (const float*)d_in[9];
    const float* g      = (const float*)d_in[10];
    const float* Wi     = (const float*)d_in[11];
    const float* bi     = (const float*)d_in[12];
    const float* ln_w   = (const float*)d_in[13];
    const float* ln_b   = (const float*)d_in[14];
    const float* Wgb    = (const float*)d_in[15];
    const float* bgb    = (const float*)d_in[16];
    const float* Wgc    = (const float*)d_in[17];
    const float* bgc    = (const float*)d_in[18];
    float* out = (float*)d_out;

    float *cln, *z, *p, *v, *uc, *zcp, *zcb, *dtb, *yv;
    float *xr, *wa, *wgb, *wgc, *wc, *we, *wi;
    cudaGetSymbolAddress((void**)&cln, g_cln);
    cudaGetSymbolAddress((void**)&z,   g_z);
    cudaGetSymbolAddress((void**)&p,   g_p);
    cudaGetSymbolAddress((void**)&v,   g_v);
    cudaGetSymbolAddress((void**)&uc,  g_uc);
    cudaGetSymbolAddress((void**)&zcp, g_zcp);
    cudaGetSymbolAddress((void**)&zcb, g_zc);
    cudaGetSymbolAddress((void**)&dtb, g_dt);
    cudaGetSymbolAddress((void**)&yv,  g_yv);
    cudaGetSymbolAddress((void**)&xr,  g_xr);
    cudaGetSymbolAddress((void**)&wa,  g_wa);
    cudaGetSymbolAddress((void**)&wgb, g_wgb);
    cudaGetSymbolAddress((void**)&wgc, g_wgc);
    cudaGetSymbolAddress((void**)&wc,  g_wc);
    cudaGetSymbolAddress((void**)&we,  g_we);
    cudaGetSymbolAddress((void**)&wi,  g_wi);

    cudaFuncSetAttribute(mma_gemm<0,4,1>,
        cudaFuncAttributeMaxDynamicSharedMemorySize, SMEM_NT4);
    cudaFuncSetAttribute(mma_gemm<1,4,1>,
        cudaFuncAttributeMaxDynamicSharedMemorySize, SMEM_NT4);
    cudaFuncSetAttribute(mma_gemm<5,4,1>,
        cudaFuncAttributeMaxDynamicSharedMemorySize, SMEM_NT4);
    cudaFuncSetAttribute(mma_gemm<0,2,KSP_>,
        cudaFuncAttributeMaxDynamicSharedMemorySize, SMEM_NT2);

    // lazy one-time side stream + events (created on the uncaptured
    // correctness call; reused as graph fork/join nodes during capture)
    static cudaStream_t s_side = nullptr;
    static cudaEvent_t evTop = nullptr, evR = nullptr, evS = nullptr;
    if (s_side == nullptr) {
        cudaStreamCreateWithFlags(&s_side, cudaStreamNonBlocking);
        cudaEventCreateWithFlags(&evTop, cudaEventDisableTiming);
        cudaEventCreateWithFlags(&evR,   cudaEventDisableTiming);
        cudaEventCreateWithFlags(&evS,   cudaEventDisableTiming);
    }

    // fork: side stream joins the capture
    cudaEventRecord(evTop, 0);
    cudaStreamWaitEvent(s_side, evTop, 0);

    // side: LayerNorm(ctx) (needs only ctx)
    ln_kernel<<<M_, 256, 0, s_side>>>(ctx, ln_w, ln_b, cln);

    // main: tf32-round x and all weight matrices
    RoundJobs rj;
    rj.j[0] = { x,   xr,  M_ * D_   / 4 };
    rj.j[1] = { Wa,  wa,  H2_ * D_  / 4 };
    rj.j[2] = { Wgb, wgb, H_ * D_   / 4 };
    rj.j[3] = { Wgc, wgc, H_ * D_   / 4 };
    rj.j[4] = { Wc,  wc,  64 * H_   / 4 };
    rj.j[5] = { We,  we,  H_ * 32   / 4 };
    rj.j[6] = { Wi,  wi,  D_ * H_   / 4 };
    round_all<<<dim3(1024, 7), 256>>>(rj);
    cudaEventRecord(evR, 0);
    cudaStreamWaitEvent(s_side, evR, 0);

    // side: merged gate GEMM -> p (cols<H) and q (cols>=H), plain+bias
    mma_gemm<5,4,1><<<dim3(H2_ / 128, M_ / 128), 512, SMEM_NT4, s_side>>>(
        cln, D_, wgb, D_, bgb, p, H_, D_,
        wgc, bgc, v);

    // main (concurrent): z = x @ Wa^T + ba      [8192, 2048]
    mma_gemm<0,4,1><<<dim3(H2_ / 128, M_ / 128), 512, SMEM_NT4>>>(
        xr, D_, wa, D_, ba, z, H2_, D_,
        nullptr, nullptr, nullptr);

    // join
    cudaEventRecord(evS, s_side);
    cudaStreamWaitEvent(0, evS, 0);

    // fused uv + conv + silu -> uc, v (v in-place over q)
    uvconv_kernel<<<(int)(((size_t)M_ * H_ / 4 + 255) / 256), 256>>>(
        z, p, v, conv_w, conv_b, uc);

    // zc = uc @ Wc^T  (split-K over 4 chunks, then reduce w/ tf32 round)
    mma_gemm<0,2,KSP_><<<dim3(KSP_, M_ / 128), 512, SMEM_NT2>>>(
        uc, H_, wc, H_, nullptr, zcp, 64, H_,
        nullptr, nullptr, nullptr);
    zc_reduce<<<(M_ * 64 / 4 + 255) / 256, 256>>>(zcp, zcb);

    // dt = softplus(zc[:, :R] @ We^T + be)      [8192, 1024]
    mma_gemm<1,4,1><<<dim3(H_ / 128, M_ / 128), 512, SMEM_NT4>>>(
        zcb, 64, we, 32, be, dtb, H_, 32,
        nullptr, nullptr, nullptr);

    // selective scan (fused skip + silu(v) gate)
    scan_kernel<<<(B_ * H_ / 2) / 8, 256>>>(uc, dtb, zcb, v, f_log, g, yv);

    // out = yv @ Wi^T + bi                      [8192, 512]
    mma_gemm<0,4,1><<<dim3(D_ / 128, M_ / 128), 512, SMEM_NT4>>>(
        yv, H_, wi, H_, bi, out, D_, H_,
        nullptr, nullptr, nullptr);
}

// round 10
// speedup vs baseline: 1.4976x; 1.3092x over previous
#include <cuda_runtime.h>
#include <cuda_fp16.h>
#include <cstdint>
#include <math.h>

// ---------------------------------------------------------------------------
// Problem constants
// ---------------------------------------------------------------------------
constexpr int B_  = 4;
constexpr int L_  = 2048;
constexpr int D_  = 512;
constexpr int H_  = 1024;   // 2*D
constexpr int S_  = 16;
constexpr int M_  = B_ * L_;        // 8192 tokens
constexpr int H2_ = 2 * H_;         // 2048
constexpr int KSP_ = 4;             // split-K factor for the zc GEMM

// ---------------------------------------------------------------------------
// Scratch (device globals; no allocation allowed)
// ---------------------------------------------------------------------------
__device__ float  g_z  [M_ * H2_];
__device__ float  g_p  [M_ * H_];    // gate pre-activation (raw)
__device__ float  g_v  [M_ * H_];    // q, then v in-place
__device__ float  g_uc [M_ * H_];    // float uc (scan)
__device__ float  g_zcp[KSP_ * M_ * 64];   // split-K partials
__device__ float  g_zc [M_ * 64];    // float zc (scan)
__device__ float  g_dt [M_ * H_];
// fp16 copies feeding GEMMs
__device__ __half g_clnh[M_ * D_];
__device__ __half g_uch [M_ * H_];
__device__ __half g_zch [M_ * 64];
__device__ __half g_yvh [M_ * H_];
__device__ __half g_xrh [M_ * D_];
__device__ __half g_wah [H2_ * D_];
__device__ __half g_wgbh[H_ * D_];
__device__ __half g_wgch[H_ * D_];
__device__ __half g_wch [64 * H_];
__device__ __half g_weh [H_ * 32];
__device__ __half g_wih [D_ * H_];

// ---------------------------------------------------------------------------
// Helpers
// ---------------------------------------------------------------------------
__device__ __forceinline__ uint32_t smem_u32(const void* p) {
    uint32_t a;
    asm("{ .reg .u64 t; cvta.to.shared.u64 t, %1; cvt.u32.u64 %0, t; }"
        : "=r"(a) : "l"(p));
    return a;
}
__device__ __forceinline__ void cpa16(uint32_t dst, const void* src) {
    asm volatile("cp.async.cg.shared.global [%0], [%1], 16;"
                 :: "r"(dst), "l"(src));
}
__device__ __forceinline__ void cpa8(uint32_t dst, const void* src) {
    asm volatile("cp.async.ca.shared.global [%0], [%1], 8;"
                 :: "r"(dst), "l"(src));
}
// round fp32 -> tf32 bits (used where scan wants tf32-consistent values)
__device__ __forceinline__ float tf32r(float x) {
    uint32_t r;
    asm("cvt.rna.tf32.f32 %0, %1;" : "=r"(r) : "f"(x));
    return __uint_as_float(r);
}
__device__ __forceinline__ void mma_f16_16x8x16(float c[4],
                                                const uint32_t a[4],
                                                const uint32_t b[2]) {
    asm volatile(
        "mma.sync.aligned.m16n8k16.row.col.f32.f16.f16.f32 "
        "{%0,%1,%2,%3}, {%4,%5,%6,%7}, {%8,%9}, {%0,%1,%2,%3};"
        : "+f"(c[0]), "+f"(c[1]), "+f"(c[2]), "+f"(c[3])
        : "r"(a[0]), "r"(a[1]), "r"(a[2]), "r"(a[3]),
          "r"(b[0]), "r"(b[1]));
}

// ---------------------------------------------------------------------------
// Batched fp16 conversion (x + all weight matrices)
// ---------------------------------------------------------------------------
struct RoundJob  { const float* src; __half* dst; int n4; };
struct RoundJobs { RoundJob j[7]; };

__global__ void round_all(RoundJobs jobs)
{
    const RoundJob J = jobs.j[blockIdx.y];
    for (int i = blockIdx.x * blockDim.x + threadIdx.x; i < J.n4;
         i += gridDim.x * blockDim.x) {
        const float4 a = ((const float4*)J.src)[i];
        __half2* o = (__half2*)J.dst + 2 * i;
        o[0] = __floats2half2_rn(a.x, a.y);
        o[1] = __floats2half2_rn(a.z, a.w);
    }
}

// ---------------------------------------------------------------------------
// fp16 mma.sync GEMM:  C[m,n] = sum_k A[m,k] * W[n,k]  (+bias, +epilogue)
// A, W are __half. 512 threads / 16 warps (4x4), block 128x(NT*32),
// warp tile 32x(NT*8). BK = 32 halfs per stage (2 MMA k-steps of K=16),
// 2 smem stages. Smem row = 32 halfs (16 words) with stride 20 words —
// fragment reads provably bank-conflict-free (banks r*20+tig mod 32).
// ACT: 0 identity  1 softplus
//      5 dual plain: cols < H_ -> (W,bias)->C, cols >= H_ -> (W2,bias2)->C2
// KSPLIT > 1: blockIdx.x selects a K-chunk, n0 = 0, C += bx * M_ * ldc.
// ---------------------------------------------------------------------------
template<int ACT, int NT, int KSPLIT>
__global__ __launch_bounds__(512, 2)
void mma_gemm(const __half* __restrict__ A, int lda,
              const __half* __restrict__ W, int ldw,
              const float* __restrict__ bias,
              float* __restrict__ C, int ldc, int K,
              const __half* __restrict__ W2,
              const float* __restrict__ bias2,
              float* __restrict__ C2)
{
    constexpr int BN = NT * 32;              // 128 or 64
    constexpr int SW = 20;                   // row stride in 4B words
    extern __shared__ uint32_t sm[];
    uint32_t* Asm = sm;                      // [2][128][SW] words
    uint32_t* Bsm = sm + 2 * 128 * SW;       // [2][BN ][SW] words

    const int tid  = threadIdx.x;
    const int warp = tid >> 5, lane = tid & 31;
    const int gid  = lane >> 2, tig = lane & 3;
    const int wm   = warp & 3,  wn  = warp >> 2;
    const int m0   = blockIdx.y * 128;

    int n0, koff, keff;
    if (KSPLIT > 1) {
        n0   = 0;
        keff = K / KSPLIT;
        koff = blockIdx.x * keff;
        C   += (size_t)blockIdx.x * M_ * ldc;
    } else {
        n0   = blockIdx.x * BN;
        keff = K;
        koff = 0;
    }

    // dual-output column split
    const __half* Wuse = W;
    const float*  buse = bias;
    float*        Cuse = C;
    int n0w = n0;
    if (ACT == 5 && n0 >= H_) {
        Wuse = W2; buse = bias2; Cuse = C2; n0w = n0 - H_;
    }

    const int mbase = wm * 32;
    const int nbase = wn * (NT * 8);

    auto sAw = [&](int st, int row, int w) -> uint32_t* {
        return Asm + (st * 128 + row) * SW + w;
    };
    auto sBw = [&](int st, int row, int w) -> uint32_t* {
        return Bsm + (st * BN + row) * SW + w;
    };

    float c[2][NT][4];
    #pragma unroll
    for (int i = 0; i < 2; i++)
        #pragma unroll
        for (int j = 0; j < NT; j++)
            #pragma unroll
            for (int q = 0; q < 4; q++) c[i][j][q] = 0.f;

    // gmem -> smem load slots (A: 16B/thread; B: 16B or 8B/thread)
    const int ar  = tid >> 2;                 // 0..127
    const int acw = (tid & 3) * 4;            // word offset in row
    const int br  = (BN == 128) ? (tid >> 2) : (tid >> 3);
    const int bcw = (BN == 128) ? (tid & 3) * 4 : (tid & 7) * 2;
    const __half* aq = A + (size_t)(m0 + ar) * lda + koff + acw * 2;
    const __half* bq = Wuse + (size_t)(n0w + br) * ldw + koff + bcw * 2;

    uint32_t adst[2], bdst[2];
    #pragma unroll
    for (int st = 0; st < 2; st++) {
        adst[st] = smem_u32(sAw(st, ar, acw));
        bdst[st] = smem_u32(sBw(st, br, bcw));
    }

    const int nk = keff >> 5;               // stages of BK=32 halfs

    auto issue_stage = [&](int t) {
        if (t < nk) {
            const int sb = t & 1;
            cpa16(adst[sb], aq + (size_t)t * 32);
            if (BN == 128) cpa16(bdst[sb], bq + (size_t)t * 32);
            else           cpa8 (bdst[sb], bq + (size_t)t * 32);
        }
        asm volatile("cp.async.commit_group;" ::: "memory");
    };

    issue_stage(0);
    issue_stage(1);

    for (int kt = 0; kt < nk; ++kt) {
        if (kt < nk - 1)
            asm volatile("cp.async.wait_group 1;" ::: "memory");
        else
            asm volatile("cp.async.wait_group 0;" ::: "memory");
        __syncthreads();
        const int st = kt & 1;

        #pragma unroll
        for (int ks = 0; ks < 2; ks++) {        // two K=16 steps
            const int wb = ks * 8;
            uint32_t af[2][4], bf[NT][2];
            #pragma unroll
            for (int ti = 0; ti < 2; ti++) {
                const int m = mbase + 16 * ti + gid;
                af[ti][0] = *sAw(st, m,     wb + tig);
                af[ti][1] = *sAw(st, m + 8, wb + tig);
                af[ti][2] = *sAw(st, m,     wb + tig + 4);
                af[ti][3] = *sAw(st, m + 8, wb + tig + 4);
            }
            #pragma unroll
            for (int tj = 0; tj < NT; tj++) {
                const int n = nbase + 8 * tj + gid;
                bf[tj][0] = *sBw(st, n, wb + tig);
                bf[tj][1] = *sBw(st, n, wb + tig + 4);
            }
            #pragma unroll
            for (int ti = 0; ti < 2; ti++)
                #pragma unroll
                for (int tj = 0; tj < NT; tj++)
                    mma_f16_16x8x16(c[ti][tj], af[ti], bf[tj]);
        }

        __syncthreads();                 // all reads of stage st done
        issue_stage(kt + 2);             // safe to overwrite buffer st
    }

    // epilogue
    #pragma unroll
    for (int ti = 0; ti < 2; ti++) {
        #pragma unroll
        for (int half = 0; half < 2; half++) {
            const int row = m0 + mbase + 16 * ti + gid + half * 8;
            #pragma unroll
            for (int tj = 0; tj < NT; tj++) {
                const int col = n0w + nbase + 8 * tj + 2 * tig;
                float v0 = c[ti][tj][half * 2 + 0];
                float v1 = c[ti][tj][half * 2 + 1];
                if (bias) { v0 += buse[col]; v1 += buse[col + 1]; }
                if (ACT == 1) {
                    v0 = (v0 > 20.f) ? v0 : log1pf(__expf(v0));
                    v1 = (v1 > 20.f) ? v1 : log1pf(__expf(v1));
                }
                float2 r; r.x = v0; r.y = v1;
                *(float2*)(Cuse + (size_t)row * ldc + col) = r;
            }
        }
    }
}

constexpr int SMEM_NT4 = (2 * 128 * 20 + 2 * 128 * 20) * 4;   // 40960
constexpr int SMEM_NT2 = (2 * 128 * 20 + 2 * 64  * 20) * 4;   // 30720

// ---------------------------------------------------------------------------
// Reduce split-K partials; writes float zc (scan) + fp16 zch (dt GEMM)
// ---------------------------------------------------------------------------
__global__ void zc_reduce(const float* __restrict__ zp,
                          float* __restrict__ zc,
                          __half* __restrict__ zch)
{
    const int idx = blockIdx.x * blockDim.x + threadIdx.x;   // float4 index
    if (idx >= M_ * 64 / 4) return;
    const float4* p0 = (const float4*)zp + idx;
    float4 a = p0[0];
    #pragma unroll
    for (int j = 1; j < KSP_; j++) {
        const float4 bq = p0[(size_t)j * (M_ * 64 / 4)];
        a.x += bq.x; a.y += bq.y; a.z += bq.z; a.w += bq.w;
    }
    __half2* oh = (__half2*)zch + 2 * idx;
    oh[0] = __floats2half2_rn(a.x, a.y);
    oh[1] = __floats2half2_rn(a.z, a.w);
    // scan path keeps tf32-grade values (same mantissa as the half copy)
    a.x = tf32r(a.x); a.y = tf32r(a.y); a.z = tf32r(a.z); a.w = tf32r(a.w);
    ((float4*)zc)[idx] = a;
}

// ---------------------------------------------------------------------------
// LayerNorm over D=512, one block (256 threads) per token -> fp16 output
// ---------------------------------------------------------------------------
__global__ void ln_kernel(const float* __restrict__ ctx,
                          const float* __restrict__ w,
                          const float* __restrict__ b,
                          __half* __restrict__ out)
{
    __shared__ float red[32];
    const int m = blockIdx.x;
    const int t = threadIdx.x;
    const float* xr = ctx + (size_t)m * D_;
    float v0 = xr[t], v1 = xr[t + 256];

    float s = v0 + v1;
    #pragma unroll
    for (int o = 16; o; o >>= 1) s += __shfl_xor_sync(0xffffffffu, s, o);
    if ((t & 31) == 0) red[t >> 5] = s;
    __syncthreads();
    if (t < 32) {
        float r = (t < 8) ? red[t] : 0.f;
        #pragma unroll
        for (int o = 4; o; o >>= 1) r += __shfl_xor_sync(0xffffffffu, r, o);
        if (t == 0) red[0] = r;
    }
    __syncthreads();
    const float mu = red[0] * (1.f / D_);
    const float d0 = v0 - mu, d1 = v1 - mu;

    float sq = d0 * d0 + d1 * d1;
    #pragma unroll
    for (int o = 16; o; o >>= 1) sq += __shfl_xor_sync(0xffffffffu, sq, o);
    __syncthreads();
    if ((t & 31) == 0) red[t >> 5] = sq;
    __syncthreads();
    if (t < 32) {
        float r = (t < 8) ? red[t] : 0.f;
        #pragma unroll
        for (int o = 4; o; o >>= 1) r += __shfl_xor_sync(0xffffffffu, r, o);
        if (t == 0) red[0] = r;
    }
    __syncthreads();
    const float inv = rsqrtf(red[0] * (1.f / D_) + 1e-5f);

    __half* orow = out + (size_t)m * D_;
    orow[t]       = __float2half_rn(d0 * inv * w[t]       + b[t]);
    orow[t + 256] = __float2half_rn(d1 * inv * w[t + 256] + b[t + 256]);
}

// ---------------------------------------------------------------------------
// Fused uv + causal depthwise conv3 + SiLU.
// Recomputes u = z1*(1+sigmoid(p)) at the 3 conv taps in registers,
// writes uc (float, for scan), uch (fp16, for zc GEMM), v = z2+q in-place.
// ---------------------------------------------------------------------------
__global__ void uvconv_kernel(const float* __restrict__ Z,
                              const float* __restrict__ P,
                              float* __restrict__ Q,     // becomes v
                              const float* __restrict__ cw,
                              const float* __restrict__ cb,
                              float* __restrict__ uc,
                              __half* __restrict__ uch)
{
    const size_t i4 = (size_t)blockIdx.x * blockDim.x + threadIdx.x;
    if (i4 >= (size_t)M_ * H_ / 4) return;
    const size_t idx = i4 * 4;
    const int    h = (int)(idx % H_);
    const size_t m = idx / H_;
    const int    l = (int)(m % L_);

    const size_t zi = m * H2_ + h;

    float4 u0, u1, u2;
    {
        const float4 p0 = *(const float4*)(P + idx);
        const float4 z0 = *(const float4*)(Z + zi);
        float* up = (float*)&u0; const float* pp = (const float*)&p0;
        const float* zp = (const float*)&z0;
        #pragma unroll
        for (int q = 0; q < 4; q++)
            up[q] = zp[q] * (1.f + 1.f / (1.f + __expf(-pp[q])));
    }
    if (l >= 1) {
        const float4 p1 = *(const float4*)(P + idx - H_);
        const float4 z1q = *(const float4*)(Z + zi - H2_);
        float* up = (float*)&u1; const float* pp = (const float*)&p1;
        const float* zp = (const float*)&z1q;
        #pragma unroll
        for (int q = 0; q < 4; q++)
            up[q] = zp[q] * (1.f + 1.f / (1.f + __expf(-pp[q])));
    } else u1 = make_float4(0.f, 0.f, 0.f, 0.f);
    if (l >= 2) {
        const float4 p2 = *(const float4*)(P + idx - 2 * H_);
        const float4 z2q = *(const float4*)(Z + zi - 2 * H2_);
        float* up = (float*)&u2; const float* pp = (const float*)&p2;
        const float* zp = (const float*)&z2q;
        #pragma unroll
        for (int q = 0; q < 4; q++)
            up[q] = zp[q] * (1.f + 1.f / (1.f + __expf(-pp[q])));
    } else u2 = make_float4(0.f, 0.f, 0.f, 0.f);

    const float* u0p = (const float*)&u0;
    const float* u1p = (const float*)&u1;
    const float* u2p = (const float*)&u2;
    float4 o; float* op = (float*)&o;
    #pragma unroll
    for (int q = 0; q < 4; q++) {
        const float r = cw[(h + q) * 3 + 0] * u2p[q]
                      + cw[(h + q) * 3 + 1] * u1p[q]
                      + cw[(h + q) * 3 + 2] * u0p[q] + cb[h + q];
        op[q] = tf32r(r / (1.f + __expf(-r)));   // silu
    }
    *(float4*)(uc + idx) = o;
    __half2* oh = (__half2*)(uch + idx);
    oh[0] = __floats2half2_rn(o.x, o.y);
    oh[1] = __floats2half2_rn(o.z, o.w);

    // v = z2 + q (in-place over q)
    {
        const float4 qv = *(const float4*)(Q + idx);
        const float4 z2v = *(const float4*)(Z + zi + H_);
        float4 vv;
        vv.x = qv.x + z2v.x; vv.y = qv.y + z2v.y;
        vv.z = qv.z + z2v.z; vv.w = qv.w + z2v.w;
        *(float4*)(Q + idx) = vv;
    }
}

// ---------------------------------------------------------------------------
// Selective scan, chunked (16 steps per chunk). Writes fp16 yv.
// ---------------------------------------------------------------------------
__global__ void scan_kernel(const float* __restrict__ uc,
                            const float* __restrict__ dt,
                            const float* __restrict__ zc,
                            const float* __restrict__ v,
                            const float* __restrict__ f_log,
                            const float* __restrict__ g,
                            __half* __restrict__ yv)
{
    const int wid  = (int)((blockIdx.x * blockDim.x + threadIdx.x) >> 5);
    const int lane = threadIdx.x & 31;
    if (wid >= B_ * H_ / 2) return;
    const int b  = wid / (H_ / 2);
    const int h0 = (wid % (H_ / 2)) * 2;
    const int hl = lane >> 4;
    const int s  = lane & 15;
    const int h  = h0 + hl;

    const float a_hs = -__expf(f_log[h * S_ + s]);
    const float gd   = g[h];
    const float* zcb  = zc + (size_t)b * L_ * 64;
    const size_t baseH = (size_t)b * L_ * H_ + h;

    float bc0[16], dt0, uc0, vv0, du0;
    {
        #pragma unroll
        for (int j = 0; j < 16; j++)
            bc0[j] = zcb[(size_t)j * 64 + 32 + lane];
        const size_t o = baseH + (size_t)s * H_;
        dt0 = dt[o]; uc0 = uc[o]; vv0 = v[o];
        du0 = dt0 * uc0;
    }

    float x = 0.f;

    for (int l0 = 0; l0 < L_; l0 += 16) {
        float bc1[16], dt1, uc1, vv1, du1;
        if (l0 + 16 < L_) {
            #pragma unroll
            for (int j = 0; j < 16; j++)
                bc1[j] = zcb[(size_t)(l0 + 16 + j) * 64 + 32 + lane];
            const size_t o = baseH + (size_t)(l0 + 16 + s) * H_;
            dt1 = dt[o]; uc1 = uc[o]; vv1 = v[o];
            du1 = dt1 * uc1;
        } else { dt1 = uc1 = vv1 = du1 = 0.f; }

        float prod[16];
        #pragma unroll
        for (int j = 0; j < 16; j++) {
            const float dtq = __shfl_sync(0xffffffffu, dt0, hl * 16 + j);
            const float duq = __shfl_sync(0xffffffffu, du0, hl * 16 + j);
            const float bm  = __shfl_sync(0xffffffffu, bc0[j], s);
            const float cm  = __shfl_sync(0xffffffffu, bc0[j], 16 + s);

            const float aa = __expf(dtq * a_hs);
            x = fmaf(aa, x, duq * bm);
            prod[j] = x * cm;
        }

        #pragma unroll
        for (int off = 8; off >= 1; off >>= 1) {
            #pragma unroll
            for (int j = 0; j < off; j++) {
                const float a = prod[j], bq = prod[j + off];
                const float send = (s & off) ? a : bq;
                const float t = __shfl_xor_sync(0xffffffffu, send, off);
                prod[j] = (s & off) ? (bq + t) : (a + t);
            }
        }

        const float sv = vv0 / (1.f + __expf(-vv0));
        yv[baseH + (size_t)(l0 + s) * H_] =
            __float2half_rn((prod[0] + uc0 * gd) * sv);

        #pragma unroll
        for (int j = 0; j < 16; j++) bc0[j] = bc1[j];
        dt0 = dt1; uc0 = uc1; vv0 = vv1; du0 = du1;
    }
}

// ---------------------------------------------------------------------------
// Launch
// ---------------------------------------------------------------------------
extern "C" void kernel_launch(void* const* d_in, const int* in_sizes, int n_in,
                              void* d_out, int out_size)
{
    const float* x      = (const float*)d_in[0];
    const float* ctx    = (const float*)d_in[1];
    const float* Wa     = (const float*)d_in[2];
    const float* ba     = (const float*)d_in[3];
    const float* conv_w = (const float*)d_in[4];
    const float* conv_b = (const float*)d_in[5];
    const float* Wc     = (const float*)d_in[6];
    const float* We     = (const float*)d_in[7];
    const float* be     = (const float*)d_in[8];
    const float* f_log  = (const float*)d_in[9];
    const float* g      = (const float*)d_in[10];
    const float* Wi     = (const float*)d_in[11];
    const float* bi     = (const float*)d_in[12];
    const float* ln_w   = (const float*)d_in[13];
    const float* ln_b   = (const float*)d_in[14];
    const float* Wgb    = (const float*)d_in[15];
    const float* bgb    = (const float*)d_in[16];
    const float* Wgc    = (const float*)d_in[17];
    const float* bgc    = (const float*)d_in[18];
    float* out = (float*)d_out;

    float *z, *p, *v, *uc, *zcp, *zcb, *dtb;
    __half *clnh, *uch, *zch, *yvh, *xrh, *wah, *wgbh, *wgch, *wch, *weh, *wih;
    cudaGetSymbolAddress((void**)&z,    g_z);
    cudaGetSymbolAddress((void**)&p,    g_p);
    cudaGetSymbolAddress((void**)&v,    g_v);
    cudaGetSymbolAddress((void**)&uc,   g_uc);
    cudaGetSymbolAddress((void**)&zcp,  g_zcp);
    cudaGetSymbolAddress((void**)&zcb,  g_zc);
    cudaGetSymbolAddress((void**)&dtb,  g_dt);
    cudaGetSymbolAddress((void**)&clnh, g_clnh);
    cudaGetSymbolAddress((void**)&uch,  g_uch);
    cudaGetSymbolAddress((void**)&zch,  g_zch);
    cudaGetSymbolAddress((void**)&yvh,  g_yvh);
    cudaGetSymbolAddress((void**)&xrh,  g_xrh);
    cudaGetSymbolAddress((void**)&wah,  g_wah);
    cudaGetSymbolAddress((void**)&wgbh, g_wgbh);
    cudaGetSymbolAddress((void**)&wgch, g_wgch);
    cudaGetSymbolAddress((void**)&wch,  g_wch);
    cudaGetSymbolAddress((void**)&weh,  g_weh);
    cudaGetSymbolAddress((void**)&wih,  g_wih);

    cudaFuncSetAttribute(mma_gemm<0,4,1>,
        cudaFuncAttributeMaxDynamicSharedMemorySize, SMEM_NT4);
    cudaFuncSetAttribute(mma_gemm<1,4,1>,
        cudaFuncAttributeMaxDynamicSharedMemorySize, SMEM_NT4);
    cudaFuncSetAttribute(mma_gemm<5,4,1>,
        cudaFuncAttributeMaxDynamicSharedMemorySize, SMEM_NT4);
    cudaFuncSetAttribute(mma_gemm<0,2,KSP_>,
        cudaFuncAttributeMaxDynamicSharedMemorySize, SMEM_NT2);

    // lazy one-time side stream + events
    static cudaStream_t s_side = nullptr;
    static cudaEvent_t evTop = nullptr, evR = nullptr, evS = nullptr;
    if (s_side == nullptr) {
        cudaStreamCreateWithFlags(&s_side, cudaStreamNonBlocking);
        cudaEventCreateWithFlags(&evTop, cudaEventDisableTiming);
        cudaEventCreateWithFlags(&evR,   cudaEventDisableTiming);
        cudaEventCreateWithFlags(&evS,   cudaEventDisableTiming);
    }

    // fork: side stream joins the capture
    cudaEventRecord(evTop, 0);
    cudaStreamWaitEvent(s_side, evTop, 0);

    // side: LayerNorm(ctx) -> fp16
    ln_kernel<<<M_, 256, 0, s_side>>>(ctx, ln_w, ln_b, clnh);

    // main: fp16-convert x and all weight matrices
    RoundJobs rj;
    rj.j[0] = { x,   xrh,  M_ * D_   / 4 };
    rj.j[1] = { Wa,  wah,  H2_ * D_  / 4 };
    rj.j[2] = { Wgb, wgbh, H_ * D_   / 4 };
    rj.j[3] = { Wgc, wgch, H_ * D_   / 4 };
    rj.j[4] = { Wc,  wch,  64 * H_   / 4 };
    rj.j[5] = { We,  weh,  H_ * 32   / 4 };
    rj.j[6] = { Wi,  wih,  D_ * H_   / 4 };
    round_all<<<dim3(1024, 7), 256>>>(rj);
    cudaEventRecord(evR, 0);
    cudaStreamWaitEvent(s_side, evR, 0);

    // side: merged gate GEMM -> p (cols<H) and q (cols>=H), plain+bias
    mma_gemm<5,4,1><<<dim3(H2_ / 128, M_ / 128), 512, SMEM_NT4, s_side>>>(
        clnh, D_, wgbh, D_, bgb, p, H_, D_,
        wgch, bgc, v);

    // main (concurrent): z = x @ Wa^T + ba      [8192, 2048]
    mma_gemm<0,4,1><<<dim3(H2_ / 128, M_ / 128), 512, SMEM_NT4>>>(
        xrh, D_, wah, D_, ba, z, H2_, D_,
        nullptr, nullptr, nullptr);

    // join
    cudaEventRecord(evS, s_side);
    cudaStreamWaitEvent(0, evS, 0);

    // fused uv + conv + silu -> uc (f32), uch (f16), v in-place
    uvconv_kernel<<<(int)(((size_t)M_ * H_ / 4 + 255) / 256), 256>>>(
        z, p, v, conv_w, conv_b, uc, uch);

    // zc = uc @ Wc^T  (split-K over 4 chunks, then reduce)
    mma_gemm<0,2,KSP_><<<dim3(KSP_, M_ / 128), 512, SMEM_NT2>>>(
        uch, H_, wch, H_, nullptr, zcp, 64, H_,
        nullptr, nullptr, nullptr);
    zc_reduce<<<(M_ * 64 / 4 + 255) / 256, 256>>>(zcp, zcb, zch);

    // dt = softplus(zc[:, :R] @ We^T + be)      [8192, 1024]
    mma_gemm<1,4,1><<<dim3(H_ / 128, M_ / 128), 512, SMEM_NT4>>>(
        zch, 64, weh, 32, be, dtb, H_, 32,
        nullptr, nullptr, nullptr);

    // selective scan (fused skip + silu(v) gate) -> fp16 yv
    scan_kernel<<<(B_ * H_ / 2) / 8, 256>>>(uc, dtb, zcb, v, f_log, g, yvh);

    // out = yv @ Wi^T + bi                      [8192, 512]
    mma_gemm<0,4,1><<<dim3(D_ / 128, M_ / 128), 512, SMEM_NT4>>>(
        yvh, H_, wih, H_, bi, out, D_, H_,
        nullptr, nullptr, nullptr);
}